// round 1
// baseline (speedup 1.0000x reference)
#include <cuda_runtime.h>
#include <math.h>

// Problem constants
#define Nn 512
#define Bb 64
#define Ff 128
#define Oo 128
#define Ee 3
#define Mrows (Nn*Bb)     // 32768 rows of x (n*B+b)
#define Jcols 512         // 3*O (supports) + O (highway)
#define K2len (Ee*Nn)     // 1536

// Scratch (static device globals — no runtime allocation)
__device__ float g_support[(size_t)Ee*Bb*Nn*Oo]; // [e,b,n,o] 48 MB
__device__ float g_t[(size_t)Mrows*Oo];          // [n,b,o] sigmoid gate
__device__ float g_h[(size_t)Mrows*Oo];          // layer-1 output [n,b,o]
__device__ float g_Wcat[Ff*Jcols];               // [f, j] concat(W[0],W[1],W[2],Wh)
__device__ float g_bcat[Jcols];

// ---- packed f32x2 helpers (Blackwell fma.rn.f32x2 — 2x fp32 FMA throughput) ----
__device__ __forceinline__ unsigned long long pack2(float lo, float hi) {
    unsigned long long r;
    asm("mov.b64 %0, {%1, %2};" : "=l"(r) : "f"(lo), "f"(hi));
    return r;
}
__device__ __forceinline__ void unpack2(unsigned long long v, float& lo, float& hi) {
    asm("mov.b64 {%0, %1}, %2;" : "=f"(lo), "=f"(hi) : "l"(v));
}
__device__ __forceinline__ unsigned long long fma2(unsigned long long a,
                                                   unsigned long long b,
                                                   unsigned long long c) {
    unsigned long long d;
    asm("fma.rn.f32x2 %0, %1, %2, %3;" : "=l"(d) : "l"(a), "l"(b), "l"(c));
    return d;
}

// ---------------------------------------------------------------------------
// Weight prep: concat W[e] (e=0..2) and Wh into g_Wcat[f][j], biases into g_bcat
// ---------------------------------------------------------------------------
__global__ void prep_weights(const float* __restrict__ W, const float* __restrict__ b,
                             const float* __restrict__ Wh, const float* __restrict__ bh) {
    int idx = blockIdx.x * blockDim.x + threadIdx.x;
    if (idx < Ff * Jcols) {
        int f = idx / Jcols, j = idx % Jcols;
        float v;
        if (j < 3 * Oo) {
            int e = j >> 7, o = j & 127;
            v = W[((size_t)e * Ff + f) * Oo + o];
        } else {
            v = Wh[(size_t)f * Oo + (j - 3 * Oo)];
        }
        g_Wcat[idx] = v;
    }
    if (idx < Jcols) {
        int j = idx;
        g_bcat[j] = (j < 3 * Oo) ? b[(j >> 7) * Oo + (j & 127)] : bh[j - 3 * Oo];
    }
}

// ---------------------------------------------------------------------------
// GEMM1: C[m, j] = sum_f X[m,f] * Wcat[f,j] + bias[j]
//   m = n*B + b (32768 rows), j in [0,512)
//   j < 384: support[e=j/128, b, n, o=j%128]
//   j >= 384: g_t[m, o] = sigmoid(c)
// Block: 64 rows x 128 cols, 256 threads, 8x4 per thread, BK=16.
// ---------------------------------------------------------------------------
__global__ __launch_bounds__(256) void gemm1(const float* __restrict__ Xin, int x_from_h) {
    const float* __restrict__ X = x_from_h ? g_h : Xin;
    __shared__ float Ast[16][64];   // A transposed: [kk][m]
    __shared__ float Bs[16][128];

    int tid = threadIdx.x;
    int tx = tid & 31, ty = tid >> 5;   // tx: o-dir (x4), ty: m-dir (x8)
    int m0 = blockIdx.x * 64;
    int jb = blockIdx.y;                // 0..3 (128-col block)
    int arow = tid >> 2, ac4 = tid & 3;

    unsigned long long acc2[8][2];
    #pragma unroll
    for (int i = 0; i < 8; ++i) { acc2[i][0] = 0ull; acc2[i][1] = 0ull; }

    for (int kt = 0; kt < Ff / 16; ++kt) {
        int kk0 = kt * 16;
        // A tile: X[m0+arow][kk0 + ac4*4 .. +3], transpose into smem
        float4 av = *(const float4*)&X[(size_t)(m0 + arow) * Ff + kk0 + ac4 * 4];
        Ast[ac4 * 4 + 0][arow] = av.x;
        Ast[ac4 * 4 + 1][arow] = av.y;
        Ast[ac4 * 4 + 2][arow] = av.z;
        Ast[ac4 * 4 + 3][arow] = av.w;
        // B tile: Wcat[(kk0+r)*512 + jb*128 + c]
        #pragma unroll
        for (int q = 0; q < 2; ++q) {
            int f4 = tid + q * 256;           // 0..511 float4 slots
            int r = f4 >> 5, c4 = f4 & 31;
            *(float4*)&Bs[r][c4 * 4] =
                *(const float4*)&g_Wcat[(size_t)(kk0 + r) * Jcols + jb * 128 + c4 * 4];
        }
        __syncthreads();
        #pragma unroll
        for (int kk = 0; kk < 16; ++kk) {
            float4 a0 = *(float4*)&Ast[kk][ty * 8];
            float4 a1 = *(float4*)&Ast[kk][ty * 8 + 4];
            ulonglong2 bp = *(ulonglong2*)&Bs[kk][tx * 4]; // (b0,b1),(b2,b3)
            float a[8] = {a0.x, a0.y, a0.z, a0.w, a1.x, a1.y, a1.z, a1.w};
            #pragma unroll
            for (int i = 0; i < 8; ++i) {
                unsigned long long ai = pack2(a[i], a[i]);
                acc2[i][0] = fma2(ai, bp.x, acc2[i][0]);
                acc2[i][1] = fma2(ai, bp.y, acc2[i][1]);
            }
        }
        __syncthreads();
    }

    int ocol = tx * 4;
    int jbase = jb * 128 + ocol;
    float bb0 = g_bcat[jbase + 0], bb1 = g_bcat[jbase + 1];
    float bb2 = g_bcat[jbase + 2], bb3 = g_bcat[jbase + 3];

    #pragma unroll
    for (int i = 0; i < 8; ++i) {
        float c0, c1, c2, c3;
        unpack2(acc2[i][0], c0, c1);
        unpack2(acc2[i][1], c2, c3);
        c0 += bb0; c1 += bb1; c2 += bb2; c3 += bb3;
        int m = m0 + ty * 8 + i;           // X-row index = n*B + b
        if (jb < 3) {
            int n = m >> 6, bidx = m & 63;
            float4 r = {c0, c1, c2, c3};
            *(float4*)&g_support[(((size_t)jb * Bb + bidx) * Nn + n) * Oo + ocol] = r;
        } else {
            float4 r;
            r.x = 1.f / (1.f + expf(-c0));
            r.y = 1.f / (1.f + expf(-c1));
            r.z = 1.f / (1.f + expf(-c2));
            r.w = 1.f / (1.f + expf(-c3));
            *(float4*)&g_t[(size_t)m * Oo + ocol] = r;
        }
    }
}

// ---------------------------------------------------------------------------
// GEMM2: out[m,b,o] = sum_{e,n} adj[e,b,m,n] * support[e,b,n,o]
// then h = relu(out)*t + x*(1-t)
// Block: (m-tile of 64, batch b). K = E*N = 1536, BK=16.
// ---------------------------------------------------------------------------
__global__ __launch_bounds__(256) void gemm2(const float* __restrict__ adj,
                                             const float* __restrict__ Xin, int x_from_h,
                                             float* __restrict__ OutExt, int out_to_h) {
    const float* __restrict__ X = x_from_h ? g_h : Xin;
    float* __restrict__ Out = out_to_h ? g_h : OutExt;

    __shared__ float Ast[16][64];
    __shared__ float Bs[16][128];

    int tid = threadIdx.x;
    int tx = tid & 31, ty = tid >> 5;
    int m0 = blockIdx.x * 64;     // node tile
    int b = blockIdx.y;           // batch
    int arow = tid >> 2, ac4 = tid & 3;

    unsigned long long acc2[8][2];
    #pragma unroll
    for (int i = 0; i < 8; ++i) { acc2[i][0] = 0ull; acc2[i][1] = 0ull; }

    for (int kt = 0; kt < K2len / 16; ++kt) {
        int kk0 = kt * 16;
        int e = kk0 >> 9, n0 = kk0 & 511;  // 16-aligned tiles never straddle e
        // A tile: adj[e,b,m0+arow, n0 + ac4*4 ..]
        const float* adjrow =
            adj + (((size_t)e * Bb + b) * Nn + (m0 + arow)) * Nn + n0;
        float4 av = *(const float4*)(adjrow + ac4 * 4);
        Ast[ac4 * 4 + 0][arow] = av.x;
        Ast[ac4 * 4 + 1][arow] = av.y;
        Ast[ac4 * 4 + 2][arow] = av.z;
        Ast[ac4 * 4 + 3][arow] = av.w;
        // B tile: support[e,b,n0+r, :]
        const float* supb = g_support + (((size_t)e * Bb + b) * Nn + n0) * Oo;
        #pragma unroll
        for (int q = 0; q < 2; ++q) {
            int f4 = tid + q * 256;
            int r = f4 >> 5, c4 = f4 & 31;
            *(float4*)&Bs[r][c4 * 4] = *(const float4*)&supb[(size_t)r * Oo + c4 * 4];
        }
        __syncthreads();
        #pragma unroll
        for (int kk = 0; kk < 16; ++kk) {
            float4 a0 = *(float4*)&Ast[kk][ty * 8];
            float4 a1 = *(float4*)&Ast[kk][ty * 8 + 4];
            ulonglong2 bp = *(ulonglong2*)&Bs[kk][tx * 4];
            float a[8] = {a0.x, a0.y, a0.z, a0.w, a1.x, a1.y, a1.z, a1.w};
            #pragma unroll
            for (int i = 0; i < 8; ++i) {
                unsigned long long ai = pack2(a[i], a[i]);
                acc2[i][0] = fma2(ai, bp.x, acc2[i][0]);
                acc2[i][1] = fma2(ai, bp.y, acc2[i][1]);
            }
        }
        __syncthreads();
    }

    int ocol = tx * 4;
    #pragma unroll
    for (int i = 0; i < 8; ++i) {
        int m = m0 + ty * 8 + i;
        size_t base = ((size_t)m * Bb + b) * Oo + ocol;
        float4 tv = *(const float4*)&g_t[base];
        float4 xv = *(const float4*)&X[base];
        float c0, c1, c2, c3;
        unpack2(acc2[i][0], c0, c1);
        unpack2(acc2[i][1], c2, c3);
        float4 r;
        r.x = fmaxf(c0, 0.f) * tv.x + xv.x * (1.f - tv.x);
        r.y = fmaxf(c1, 0.f) * tv.y + xv.y * (1.f - tv.y);
        r.z = fmaxf(c2, 0.f) * tv.z + xv.z * (1.f - tv.z);
        r.w = fmaxf(c3, 0.f) * tv.w + xv.w * (1.f - tv.w);
        *(float4*)&Out[base] = r;
    }
}

extern "C" void kernel_launch(void* const* d_in, const int* in_sizes, int n_in,
                              void* d_out, int out_size) {
    const float* x   = (const float*)d_in[0];
    const float* adj = (const float*)d_in[1];
    const float* W1  = (const float*)d_in[2];
    const float* b1  = (const float*)d_in[3];
    const float* Wh1 = (const float*)d_in[4];
    const float* bh1 = (const float*)d_in[5];
    const float* W2  = (const float*)d_in[6];
    const float* b2  = (const float*)d_in[7];
    const float* Wh2 = (const float*)d_in[8];
    const float* bh2 = (const float*)d_in[9];
    float* out = (float*)d_out;

    dim3 g1(Mrows / 64, Jcols / 128);   // (512, 4)
    dim3 g2(Nn / 64, Bb);               // (8, 64)

    // Layer 1
    prep_weights<<<(Ff * Jcols) / 256, 256>>>(W1, b1, Wh1, bh1);
    gemm1<<<g1, 256>>>(x, 0);
    gemm2<<<g2, 256>>>(adj, x, 0, nullptr, 1);   // -> g_h
    // Layer 2
    prep_weights<<<(Ff * Jcols) / 256, 256>>>(W2, b2, Wh2, bh2);
    gemm1<<<g1, 256>>>(nullptr, 1);              // X = g_h
    gemm2<<<g2, 256>>>(adj, nullptr, 1, out, 0); // X = g_h, -> d_out
}

// round 3
// speedup vs baseline: 1.7100x; 1.7100x over previous
#include <cuda_runtime.h>
#include <cuda_bf16.h>
#include <math.h>
#include <stdint.h>

// Problem constants
#define Nn 512
#define Bb 64
#define Ff 128
#define Oo 128
#define Ee 3
#define Mrows (Nn*Bb)     // 32768
#define Jcols 512         // 3*O + O(highway)

// Scratch (static device globals)
__device__ float g_t[(size_t)Mrows*Oo];          // sigmoid gate [n*B+b, o]
__device__ float g_h[(size_t)Mrows*Oo];          // layer-1 output
__device__ float g_Wcat[Ff*Jcols];
__device__ float g_bcat[Jcols];
// support in bf16 hi/lo planes: [e,b,n,o]
__device__ __nv_bfloat16 g_supH[(size_t)Ee*Bb*Nn*Oo];
__device__ __nv_bfloat16 g_supL[(size_t)Ee*Bb*Nn*Oo];

// ---- packed f32x2 helpers (gemm1 FFMA path) ----
__device__ __forceinline__ unsigned long long pack2(float lo, float hi) {
    unsigned long long r;
    asm("mov.b64 %0, {%1, %2};" : "=l"(r) : "f"(lo), "f"(hi));
    return r;
}
__device__ __forceinline__ void unpack2(unsigned long long v, float& lo, float& hi) {
    asm("mov.b64 {%0, %1}, %2;" : "=f"(lo), "=f"(hi) : "l"(v));
}
__device__ __forceinline__ unsigned long long fma2(unsigned long long a,
                                                   unsigned long long b,
                                                   unsigned long long c) {
    unsigned long long d;
    asm("fma.rn.f32x2 %0, %1, %2, %3;" : "=l"(d) : "l"(a), "l"(b), "l"(c));
    return d;
}

// ---- bf16 split: (x,y) -> packed hi pair + packed lo pair ----
__device__ __forceinline__ void cvt_split(float x, float y, uint32_t& hi, uint32_t& lo) {
    __nv_bfloat162 h = __floats2bfloat162_rn(x, y);
    float2 hf = __bfloat1622float2(h);
    __nv_bfloat162 l = __floats2bfloat162_rn(x - hf.x, y - hf.y);
    hi = *reinterpret_cast<uint32_t*>(&h);
    lo = *reinterpret_cast<uint32_t*>(&l);
}

__device__ __forceinline__ uint32_t smem_u32(const void* p) {
    uint32_t a;
    asm("{ .reg .u64 t; cvta.to.shared.u64 t, %1; cvt.u32.u64 %0, t; }" : "=r"(a) : "l"(p));
    return a;
}

// ---- warp-level MMA primitives (no arch-suffix needed; sm_80+) ----
__device__ __forceinline__ void ldsm4(uint32_t r[4], uint32_t addr) {
    asm volatile("ldmatrix.sync.aligned.m8n8.x4.shared.b16 {%0,%1,%2,%3}, [%4];"
                 : "=r"(r[0]), "=r"(r[1]), "=r"(r[2]), "=r"(r[3]) : "r"(addr));
}
__device__ __forceinline__ void ldsm4t(uint32_t r[4], uint32_t addr) {
    asm volatile("ldmatrix.sync.aligned.m8n8.x4.trans.shared.b16 {%0,%1,%2,%3}, [%4];"
                 : "=r"(r[0]), "=r"(r[1]), "=r"(r[2]), "=r"(r[3]) : "r"(addr));
}
__device__ __forceinline__ void mma16816(float c[4], const uint32_t a[4], const uint32_t b[2]) {
    asm volatile(
        "mma.sync.aligned.m16n8k16.row.col.f32.bf16.bf16.f32 "
        "{%0,%1,%2,%3}, {%4,%5,%6,%7}, {%8,%9}, {%0,%1,%2,%3};"
        : "+f"(c[0]), "+f"(c[1]), "+f"(c[2]), "+f"(c[3])
        : "r"(a[0]), "r"(a[1]), "r"(a[2]), "r"(a[3]), "r"(b[0]), "r"(b[1]));
}

// ---------------------------------------------------------------------------
// prep_weights (unchanged)
// ---------------------------------------------------------------------------
__global__ void prep_weights(const float* __restrict__ W, const float* __restrict__ b,
                             const float* __restrict__ Wh, const float* __restrict__ bh) {
    int idx = blockIdx.x * blockDim.x + threadIdx.x;
    if (idx < Ff * Jcols) {
        int f = idx / Jcols, j = idx % Jcols;
        float v;
        if (j < 3 * Oo) {
            int e = j >> 7, o = j & 127;
            v = W[((size_t)e * Ff + f) * Oo + o];
        } else {
            v = Wh[(size_t)f * Oo + (j - 3 * Oo)];
        }
        g_Wcat[idx] = v;
    }
    if (idx < Jcols) {
        int j = idx;
        g_bcat[j] = (j < 3 * Oo) ? b[(j >> 7) * Oo + (j & 127)] : bh[j - 3 * Oo];
    }
}

// ---------------------------------------------------------------------------
// GEMM1 (FFMA f32x2, proven in R1): writes g_supH/g_supL (bf16 hi/lo) + g_t
// ---------------------------------------------------------------------------
__global__ __launch_bounds__(256) void gemm1(const float* __restrict__ Xin, int x_from_h) {
    const float* __restrict__ X = x_from_h ? g_h : Xin;
    __shared__ float Ast[16][64];
    __shared__ float Bs[16][128];

    int tid = threadIdx.x;
    int tx = tid & 31, ty = tid >> 5;
    int m0 = blockIdx.x * 64;
    int jb = blockIdx.y;
    int arow = tid >> 2, ac4 = tid & 3;

    unsigned long long acc2[8][2];
    #pragma unroll
    for (int i = 0; i < 8; ++i) { acc2[i][0] = 0ull; acc2[i][1] = 0ull; }

    for (int kt = 0; kt < Ff / 16; ++kt) {
        int kk0 = kt * 16;
        float4 av = *(const float4*)&X[(size_t)(m0 + arow) * Ff + kk0 + ac4 * 4];
        Ast[ac4 * 4 + 0][arow] = av.x;
        Ast[ac4 * 4 + 1][arow] = av.y;
        Ast[ac4 * 4 + 2][arow] = av.z;
        Ast[ac4 * 4 + 3][arow] = av.w;
        #pragma unroll
        for (int q = 0; q < 2; ++q) {
            int f4 = tid + q * 256;
            int r = f4 >> 5, c4 = f4 & 31;
            *(float4*)&Bs[r][c4 * 4] =
                *(const float4*)&g_Wcat[(size_t)(kk0 + r) * Jcols + jb * 128 + c4 * 4];
        }
        __syncthreads();
        #pragma unroll
        for (int kk = 0; kk < 16; ++kk) {
            float4 a0 = *(float4*)&Ast[kk][ty * 8];
            float4 a1 = *(float4*)&Ast[kk][ty * 8 + 4];
            ulonglong2 bp = *(ulonglong2*)&Bs[kk][tx * 4];
            float a[8] = {a0.x, a0.y, a0.z, a0.w, a1.x, a1.y, a1.z, a1.w};
            #pragma unroll
            for (int i = 0; i < 8; ++i) {
                unsigned long long ai = pack2(a[i], a[i]);
                acc2[i][0] = fma2(ai, bp.x, acc2[i][0]);
                acc2[i][1] = fma2(ai, bp.y, acc2[i][1]);
            }
        }
        __syncthreads();
    }

    int ocol = tx * 4;
    int jbase = jb * 128 + ocol;
    float bb0 = g_bcat[jbase + 0], bb1 = g_bcat[jbase + 1];
    float bb2 = g_bcat[jbase + 2], bb3 = g_bcat[jbase + 3];

    #pragma unroll
    for (int i = 0; i < 8; ++i) {
        float c0, c1, c2, c3;
        unpack2(acc2[i][0], c0, c1);
        unpack2(acc2[i][1], c2, c3);
        c0 += bb0; c1 += bb1; c2 += bb2; c3 += bb3;
        int m = m0 + ty * 8 + i;          // m = n*B + b
        if (jb < 3) {
            int n = m >> 6, bidx = m & 63;
            uint32_t h01, l01, h23, l23;
            cvt_split(c0, c1, h01, l01);
            cvt_split(c2, c3, h23, l23);
            size_t off = (((size_t)jb * Bb + bidx) * Nn + n) * Oo + ocol;
            *(uint2*)&g_supH[off] = make_uint2(h01, h23);
            *(uint2*)&g_supL[off] = make_uint2(l01, l23);
        } else {
            float4 r;
            r.x = 1.f / (1.f + expf(-c0));
            r.y = 1.f / (1.f + expf(-c1));
            r.z = 1.f / (1.f + expf(-c2));
            r.w = 1.f / (1.f + expf(-c3));
            *(float4*)&g_t[(size_t)m * Oo + ocol] = r;
        }
    }
}

// ---------------------------------------------------------------------------
// GEMM2 on mma.sync (bf16 3-pass): out[m,b,:] = relu(sum adj*sup) highway-gated
// CTA: 128(m) x 128(o), batch b. 8 warps (2x4), 64x32 warp tiles, BK=32.
// ---------------------------------------------------------------------------
#define BM2 128
#define BK2 32
#define ASTR 40    // A smem row stride in bf16 elems (80 B) -> conflict-free LDSM
#define BSTR 136   // B smem row stride in bf16 elems (272 B)
#define NCH 48     // K chunks: 1536/32

__global__ __launch_bounds__(256) void gemm2_mma(const float* __restrict__ adj,
                                                 const float* __restrict__ Xin, int x_from_h,
                                                 float* __restrict__ OutExt, int out_to_h) {
    __shared__ __nv_bfloat16 AsH[BM2 * ASTR];
    __shared__ __nv_bfloat16 AsL[BM2 * ASTR];
    __shared__ __nv_bfloat16 BsH[BK2 * BSTR];
    __shared__ __nv_bfloat16 BsL[BK2 * BSTR];

    const float* __restrict__ X = x_from_h ? g_h : Xin;
    float* __restrict__ Out = out_to_h ? g_h : OutExt;

    int tid = threadIdx.x, lane = tid & 31, wid = tid >> 5;
    int wm = wid & 1, wn = wid >> 1;          // 2 x 4 warp grid
    int m0 = blockIdx.x * BM2, b = blockIdx.y;

    float acc[4][4][4];
    #pragma unroll
    for (int mi = 0; mi < 4; ++mi)
        #pragma unroll
        for (int ni = 0; ni < 4; ++ni)
            #pragma unroll
            for (int r = 0; r < 4; ++r) acc[mi][ni][r] = 0.f;

    // load-assignment indices
    int arow[4], ac4[4];
    #pragma unroll
    for (int q = 0; q < 4; ++q) { int i = q * 256 + tid; arow[q] = i >> 3; ac4[q] = i & 7; }
    int brow[2], bc8[2];
    #pragma unroll
    for (int q = 0; q < 2; ++q) { int i = q * 256 + tid; brow[q] = i >> 4; bc8[q] = i & 15; }

    float4 av[4];
    uint4 bhv[2], blv[2];

    auto loadg = [&](int c) {
        int e = c >> 4, n0 = (c & 15) * 32;
        #pragma unroll
        for (int q = 0; q < 4; ++q)
            av[q] = *(const float4*)&adj[(((size_t)e * Bb + b) * Nn + (m0 + arow[q])) * Nn
                                         + n0 + ac4[q] * 4];
        size_t sb = (((size_t)e * Bb + b) * Nn + n0) * Oo;
        #pragma unroll
        for (int q = 0; q < 2; ++q) {
            size_t idx = sb + (size_t)brow[q] * Oo + bc8[q] * 8;
            bhv[q] = *(const uint4*)&g_supH[idx];
            blv[q] = *(const uint4*)&g_supL[idx];
        }
    };
    auto fillsmem = [&]() {
        #pragma unroll
        for (int q = 0; q < 4; ++q) {
            uint32_t h01, l01, h23, l23;
            cvt_split(av[q].x, av[q].y, h01, l01);
            cvt_split(av[q].z, av[q].w, h23, l23);
            int off = arow[q] * ASTR + ac4[q] * 4;
            *(uint2*)&AsH[off] = make_uint2(h01, h23);
            *(uint2*)&AsL[off] = make_uint2(l01, l23);
        }
        #pragma unroll
        for (int q = 0; q < 2; ++q) {
            int off = brow[q] * BSTR + bc8[q] * 8;
            *(uint4*)&BsH[off] = bhv[q];
            *(uint4*)&BsL[off] = blv[q];
        }
    };

    uint32_t aH = smem_u32(AsH), aL = smem_u32(AsL);
    uint32_t bH = smem_u32(BsH), bL = smem_u32(BsL);

    auto compute = [&]() {
        #pragma unroll
        for (int ks = 0; ks < 2; ++ks) {
            int k0 = ks * 16;
            uint32_t ah[4][4], al[4][4], bhf[4][2], blf[4][2];
            uint32_t abase = ((wm * 64 + (lane & 15)) * ASTR + k0 + ((lane >> 4) << 3)) * 2;
            #pragma unroll
            for (int mi = 0; mi < 4; ++mi) {
                ldsm4(ah[mi], aH + abase + mi * 16 * ASTR * 2);
                ldsm4(al[mi], aL + abase + mi * 16 * ASTR * 2);
            }
            uint32_t bbase = ((k0 + (lane & 15)) * BSTR + wn * 32 + ((lane >> 4) << 3)) * 2;
            #pragma unroll
            for (int g = 0; g < 2; ++g) {
                uint32_t r[4];
                ldsm4t(r, bH + bbase + g * 32);
                bhf[g*2][0] = r[0]; bhf[g*2][1] = r[1];
                bhf[g*2+1][0] = r[2]; bhf[g*2+1][1] = r[3];
                ldsm4t(r, bL + bbase + g * 32);
                blf[g*2][0] = r[0]; blf[g*2][1] = r[1];
                blf[g*2+1][0] = r[2]; blf[g*2+1][1] = r[3];
            }
            #pragma unroll
            for (int mi = 0; mi < 4; ++mi)
                #pragma unroll
                for (int ni = 0; ni < 4; ++ni) {
                    mma16816(acc[mi][ni], ah[mi], bhf[ni]);   // HH
                    mma16816(acc[mi][ni], ah[mi], blf[ni]);   // HL
                    mma16816(acc[mi][ni], al[mi], bhf[ni]);   // LH
                }
        }
    };

    loadg(0);
    fillsmem();
    __syncthreads();
    for (int c = 0; c < NCH; ++c) {
        if (c + 1 < NCH) loadg(c + 1);
        compute();
        __syncthreads();
        if (c + 1 < NCH) { fillsmem(); __syncthreads(); }
    }

    // epilogue: relu + highway gate
    #pragma unroll
    for (int mi = 0; mi < 4; ++mi) {
        #pragma unroll
        for (int ni = 0; ni < 4; ++ni) {
            int r0 = m0 + wm * 64 + mi * 16 + (lane >> 2);
            int col = wn * 32 + ni * 8 + (lane & 3) * 2;
            #pragma unroll
            for (int h = 0; h < 2; ++h) {
                int row = r0 + h * 8;
                float d0 = acc[mi][ni][h * 2 + 0];
                float d1 = acc[mi][ni][h * 2 + 1];
                size_t base = ((size_t)row * Bb + b) * Oo + col;
                float2 tv = *(const float2*)&g_t[base];
                float2 xv = *(const float2*)&X[base];
                float2 r;
                r.x = fmaxf(d0, 0.f) * tv.x + xv.x * (1.f - tv.x);
                r.y = fmaxf(d1, 0.f) * tv.y + xv.y * (1.f - tv.y);
                *(float2*)&Out[base] = r;
            }
        }
    }
}

extern "C" void kernel_launch(void* const* d_in, const int* in_sizes, int n_in,
                              void* d_out, int out_size) {
    const float* x   = (const float*)d_in[0];
    const float* adj = (const float*)d_in[1];
    const float* W1  = (const float*)d_in[2];
    const float* b1  = (const float*)d_in[3];
    const float* Wh1 = (const float*)d_in[4];
    const float* bh1 = (const float*)d_in[5];
    const float* W2  = (const float*)d_in[6];
    const float* b2  = (const float*)d_in[7];
    const float* Wh2 = (const float*)d_in[8];
    const float* bh2 = (const float*)d_in[9];
    float* out = (float*)d_out;

    dim3 g1(Mrows / 64, Jcols / 128);   // (512, 4)
    dim3 g2(Nn / BM2, Bb);              // (4, 64)

    // Layer 1
    prep_weights<<<(Ff * Jcols) / 256, 256>>>(W1, b1, Wh1, bh1);
    gemm1<<<g1, 256>>>(x, 0);
    gemm2_mma<<<g2, 256>>>(adj, x, 0, nullptr, 1);   // -> g_h
    // Layer 2
    prep_weights<<<(Ff * Jcols) / 256, 256>>>(W2, b2, Wh2, bh2);
    gemm1<<<g1, 256>>>(nullptr, 1);
    gemm2_mma<<<g2, 256>>>(adj, nullptr, 1, out, 0); // -> d_out
}

// round 5
// speedup vs baseline: 1.9593x; 1.1458x over previous
#include <cuda_runtime.h>
#include <cuda_bf16.h>
#include <math.h>
#include <stdint.h>

// Problem constants
#define Nn 512
#define Bb 64
#define Ff 128
#define Oo 128
#define Ee 3
#define Mrows (Nn*Bb)     // 32768
#define Jcols 512         // 3*O + O(highway)

// Scratch (static device globals)
__device__ float g_t[(size_t)Mrows*Oo];          // sigmoid gate [m, o]
__device__ float g_h[(size_t)Mrows*Oo];          // layer-1 output fp32 (highway X)
__device__ float g_bcat[Jcols];
__device__ __nv_bfloat16 g_WcatH[Ff*Jcols];
__device__ __nv_bfloat16 g_WcatL[Ff*Jcols];
__device__ __nv_bfloat16 g_xH[(size_t)Mrows*Ff];  // layer-1 X planes
__device__ __nv_bfloat16 g_xL[(size_t)Mrows*Ff];
__device__ __nv_bfloat16 g_hH[(size_t)Mrows*Ff];  // layer-2 X planes
__device__ __nv_bfloat16 g_hL[(size_t)Mrows*Ff];
// support planes [e,b,n,o]
__device__ __nv_bfloat16 g_supH[(size_t)Ee*Bb*Nn*Oo];
__device__ __nv_bfloat16 g_supL[(size_t)Ee*Bb*Nn*Oo];

// ---- bf16 split: (x,y) -> packed hi pair + packed lo pair ----
__device__ __forceinline__ void cvt_split(float x, float y, uint32_t& hi, uint32_t& lo) {
    __nv_bfloat162 h = __floats2bfloat162_rn(x, y);
    float2 hf = __bfloat1622float2(h);
    __nv_bfloat162 l = __floats2bfloat162_rn(x - hf.x, y - hf.y);
    hi = *reinterpret_cast<uint32_t*>(&h);
    lo = *reinterpret_cast<uint32_t*>(&l);
}

__device__ __forceinline__ uint32_t smem_u32(const void* p) {
    uint32_t a;
    asm("{ .reg .u64 t; cvta.to.shared.u64 t, %1; cvt.u32.u64 %0, t; }" : "=r"(a) : "l"(p));
    return a;
}

// ---- cp.async ----
__device__ __forceinline__ void cpa16(uint32_t saddr, const void* g) {
    asm volatile("cp.async.cg.shared.global [%0], [%1], 16;" :: "r"(saddr), "l"(g));
}
__device__ __forceinline__ void cpa_commit() {
    asm volatile("cp.async.commit_group;" ::: "memory");
}
__device__ __forceinline__ void cpa_wait0() {
    asm volatile("cp.async.wait_group 0;" ::: "memory");
}

// ---- warp-level MMA primitives ----
__device__ __forceinline__ void ldsm4(uint32_t r[4], uint32_t addr) {
    asm volatile("ldmatrix.sync.aligned.m8n8.x4.shared.b16 {%0,%1,%2,%3}, [%4];"
                 : "=r"(r[0]), "=r"(r[1]), "=r"(r[2]), "=r"(r[3]) : "r"(addr));
}
__device__ __forceinline__ void ldsm4t(uint32_t r[4], uint32_t addr) {
    asm volatile("ldmatrix.sync.aligned.m8n8.x4.trans.shared.b16 {%0,%1,%2,%3}, [%4];"
                 : "=r"(r[0]), "=r"(r[1]), "=r"(r[2]), "=r"(r[3]) : "r"(addr));
}
__device__ __forceinline__ void mma16816(float c[4], const uint32_t a[4], const uint32_t b[2]) {
    asm volatile(
        "mma.sync.aligned.m16n8k16.row.col.f32.bf16.bf16.f32 "
        "{%0,%1,%2,%3}, {%4,%5,%6,%7}, {%8,%9}, {%0,%1,%2,%3};"
        : "+f"(c[0]), "+f"(c[1]), "+f"(c[2]), "+f"(c[3])
        : "r"(a[0]), "r"(a[1]), "r"(a[2]), "r"(a[3]), "r"(b[0]), "r"(b[1]));
}

// ---- shared tile geometry (both GEMMs) ----
#define ASTR 40       // A smem row stride (bf16 elems), 80 B
#define BSTR 136      // B smem row stride (bf16 elems), 272 B
#define A_PLANE 10240 // 128*40*2 bytes
#define B_PLANE 8704  // 32*136*2 bytes
#define AH_OFF 0
#define AL_OFF A_PLANE
#define BH_OFF (2*A_PLANE)
#define BL_OFF (2*A_PLANE + B_PLANE)
#define BUFSTRIDE (2*A_PLANE + 2*B_PLANE)   // 37888
#define SMEM_TOTAL (2*BUFSTRIDE)            // 75776

// 3-pass MMA compute on one staged buffer. 2x4 warp grid, 64x32 warp tiles.
__device__ __forceinline__ void mma_compute(uint32_t sb, int lane, int wm, int wn,
                                            float acc[4][4][4]) {
    #pragma unroll
    for (int ks = 0; ks < 2; ++ks) {
        int k0 = ks * 16;
        uint32_t ah[4][4], al[4][4], bhf[4][2], blf[4][2];
        uint32_t abase = sb + ((wm * 64 + (lane & 15)) * ASTR + k0 + ((lane >> 4) << 3)) * 2;
        #pragma unroll
        for (int mi = 0; mi < 4; ++mi) {
            ldsm4(ah[mi], abase + AH_OFF + mi * 16 * ASTR * 2);
            ldsm4(al[mi], abase + AL_OFF + mi * 16 * ASTR * 2);
        }
        uint32_t bbase = sb + ((k0 + (lane & 15)) * BSTR + wn * 32 + ((lane >> 4) << 3)) * 2;
        #pragma unroll
        for (int g = 0; g < 2; ++g) {
            uint32_t r[4];
            ldsm4t(r, bbase + BH_OFF + g * 32);
            bhf[g*2][0] = r[0]; bhf[g*2][1] = r[1];
            bhf[g*2+1][0] = r[2]; bhf[g*2+1][1] = r[3];
            ldsm4t(r, bbase + BL_OFF + g * 32);
            blf[g*2][0] = r[0]; blf[g*2][1] = r[1];
            blf[g*2+1][0] = r[2]; blf[g*2+1][1] = r[3];
        }
        #pragma unroll
        for (int mi = 0; mi < 4; ++mi)
            #pragma unroll
            for (int ni = 0; ni < 4; ++ni) {
                mma16816(acc[mi][ni], ah[mi], bhf[ni]);   // HH
                mma16816(acc[mi][ni], ah[mi], blf[ni]);   // HL
                mma16816(acc[mi][ni], al[mi], bhf[ni]);   // LH
            }
    }
}

// ---------------------------------------------------------------------------
// prep_weights: W/Wh -> bf16 hi/lo planes [f][j], biases fp32
// ---------------------------------------------------------------------------
__global__ void prep_weights(const float* __restrict__ W, const float* __restrict__ b,
                             const float* __restrict__ Wh, const float* __restrict__ bh) {
    int idx = blockIdx.x * blockDim.x + threadIdx.x;   // over Ff*Jcols/2 pairs
    if (idx < Ff * Jcols / 2) {
        int f = idx / (Jcols / 2), jp = idx % (Jcols / 2);
        int j = jp * 2;
        float v0, v1;
        if (j < 3 * Oo) {
            int e = j >> 7, o = j & 127;
            v0 = W[((size_t)e * Ff + f) * Oo + o];
            v1 = W[((size_t)e * Ff + f) * Oo + o + 1];
        } else {
            v0 = Wh[(size_t)f * Oo + (j - 3 * Oo)];
            v1 = Wh[(size_t)f * Oo + (j - 3 * Oo) + 1];
        }
        uint32_t hi, lo;
        cvt_split(v0, v1, hi, lo);
        *(uint32_t*)&g_WcatH[f * Jcols + j] = hi;
        *(uint32_t*)&g_WcatL[f * Jcols + j] = lo;
    }
    if (idx < Jcols) {
        int j = idx;
        g_bcat[j] = (j < 3 * Oo) ? b[(j >> 7) * Oo + (j & 127)] : bh[j - 3 * Oo];
    }
}

// ---------------------------------------------------------------------------
// x_split: fp32 [m,f] -> bf16 hi/lo planes (layer-1 X)
// ---------------------------------------------------------------------------
__global__ void x_split(const float* __restrict__ x) {
    int i = blockIdx.x * blockDim.x + threadIdx.x;   // over float4 slots
    float4 v = ((const float4*)x)[i];
    uint32_t h01, l01, h23, l23;
    cvt_split(v.x, v.y, h01, l01);
    cvt_split(v.z, v.w, h23, l23);
    ((uint2*)g_xH)[i] = make_uint2(h01, h23);
    ((uint2*)g_xL)[i] = make_uint2(l01, l23);
}

// ---------------------------------------------------------------------------
// GEMM1 on mma.sync: C[m, j] = X[m,:] @ Wcat[:, jb*128..] + bias
// grid (Mrows/128, 4). A and B via cp.async (all bf16 in gmem). NCH=4.
// ---------------------------------------------------------------------------
__global__ __launch_bounds__(256) void gemm1_mma(int x_from_h) {
    extern __shared__ char smem[];
    const __nv_bfloat16* __restrict__ XH = x_from_h ? g_hH : g_xH;
    const __nv_bfloat16* __restrict__ XL = x_from_h ? g_hL : g_xL;
    uint32_t sbase = smem_u32(smem);

    int tid = threadIdx.x, lane = tid & 31, wid = tid >> 5;
    int wm = wid & 1, wn = wid >> 1;
    int m0 = blockIdx.x * 128, jb = blockIdx.y;

    float acc[4][4][4];
    #pragma unroll
    for (int mi = 0; mi < 4; ++mi)
        #pragma unroll
        for (int ni = 0; ni < 4; ++ni)
            #pragma unroll
            for (int r = 0; r < 4; ++r) acc[mi][ni][r] = 0.f;

    auto issue = [&](int c) {
        uint32_t sb = sbase + (c & 1) * BUFSTRIDE;
        int k0 = c * 32;
        #pragma unroll
        for (int q = 0; q < 2; ++q) {           // A: 128 rows x 32 k, 4 uint4/row
            int i = q * 256 + tid;
            int row = i >> 2, c8 = i & 3;
            uint32_t so = row * (ASTR * 2) + c8 * 16;
            size_t go = (size_t)(m0 + row) * Ff + k0 + c8 * 8;
            cpa16(sb + AH_OFF + so, XH + go);
            cpa16(sb + AL_OFF + so, XL + go);
        }
        #pragma unroll
        for (int q = 0; q < 2; ++q) {           // B: 32 rows x 128 cols
            int i = q * 256 + tid;
            int row = i >> 4, c8 = i & 15;
            uint32_t so = row * (BSTR * 2) + c8 * 16;
            size_t go = (size_t)(k0 + row) * Jcols + jb * 128 + c8 * 8;
            cpa16(sb + BH_OFF + so, g_WcatH + go);
            cpa16(sb + BL_OFF + so, g_WcatL + go);
        }
        cpa_commit();
    };

    issue(0);
    #pragma unroll
    for (int c = 0; c < 4; ++c) {
        cpa_wait0();
        __syncthreads();
        if (c + 1 < 4) issue(c + 1);
        mma_compute(sbase + (c & 1) * BUFSTRIDE, lane, wm, wn, acc);
        if (c + 1 < 4) __syncthreads();   // buffer c&1 may be re-staged at c+2? no: 2 bufs, c+1 uses other buf; sync guards reuse of this buf at c+2 via next wait+sync; keep minimal safety
    }

    // epilogue: add bias; jb<3 -> split to sup planes; jb==3 -> sigmoid -> g_t
    #pragma unroll
    for (int mi = 0; mi < 4; ++mi) {
        #pragma unroll
        for (int ni = 0; ni < 4; ++ni) {
            int col = wn * 32 + ni * 8 + (lane & 3) * 2;
            float bb0 = g_bcat[jb * 128 + col], bb1 = g_bcat[jb * 128 + col + 1];
            #pragma unroll
            for (int h = 0; h < 2; ++h) {
                int m = m0 + wm * 64 + mi * 16 + (lane >> 2) + h * 8;
                float d0 = acc[mi][ni][h * 2 + 0] + bb0;
                float d1 = acc[mi][ni][h * 2 + 1] + bb1;
                if (jb < 3) {
                    int n = m >> 6, bidx = m & 63;
                    uint32_t hi, lo;
                    cvt_split(d0, d1, hi, lo);
                    size_t off = (((size_t)jb * Bb + bidx) * Nn + n) * Oo + col;
                    *(uint32_t*)&g_supH[off] = hi;
                    *(uint32_t*)&g_supL[off] = lo;
                } else {
                    float2 r;
                    r.x = 1.f / (1.f + expf(-d0));
                    r.y = 1.f / (1.f + expf(-d1));
                    *(float2*)&g_t[(size_t)m * Oo + col] = r;
                }
            }
        }
    }
}

// ---------------------------------------------------------------------------
// GEMM2 on mma.sync: out[m,b,:] = relu(sum adj*sup) highway-gated
// grid (4, 64). B via cp.async; A (adj fp32) register-staged + cvt. NCH=48.
// ---------------------------------------------------------------------------
#define NCH2 48

__global__ __launch_bounds__(256) void gemm2_mma(const float* __restrict__ adj,
                                                 const float* __restrict__ Xin, int x_from_h,
                                                 float* __restrict__ OutExt, int out_to_h) {
    extern __shared__ char smem[];
    const float* __restrict__ X = x_from_h ? g_h : Xin;
    float* __restrict__ Out = out_to_h ? g_h : OutExt;
    uint32_t sbase = smem_u32(smem);

    int tid = threadIdx.x, lane = tid & 31, wid = tid >> 5;
    int wm = wid & 1, wn = wid >> 1;
    int m0 = blockIdx.x * 128, b = blockIdx.y;

    float acc[4][4][4];
    #pragma unroll
    for (int mi = 0; mi < 4; ++mi)
        #pragma unroll
        for (int ni = 0; ni < 4; ++ni)
            #pragma unroll
            for (int r = 0; r < 4; ++r) acc[mi][ni][r] = 0.f;

    int arow[4], ac4[4];
    #pragma unroll
    for (int q = 0; q < 4; ++q) { int i = q * 256 + tid; arow[q] = i >> 3; ac4[q] = i & 7; }
    float4 av[4];

    auto issueB = [&](int c) {
        uint32_t sb = sbase + (c & 1) * BUFSTRIDE;
        int e = c >> 4, n0 = (c & 15) * 32;
        size_t gb = (((size_t)e * Bb + b) * Nn + n0) * Oo;
        #pragma unroll
        for (int q = 0; q < 2; ++q) {
            int i = q * 256 + tid;
            int row = i >> 4, c8 = i & 15;
            uint32_t so = row * (BSTR * 2) + c8 * 16;
            size_t go = gb + (size_t)row * Oo + c8 * 8;
            cpa16(sb + BH_OFF + so, g_supH + go);
            cpa16(sb + BL_OFF + so, g_supL + go);
        }
        cpa_commit();
    };
    auto loadA = [&](int c) {
        int e = c >> 4, n0 = (c & 15) * 32;
        const float* ab = adj + (((size_t)e * Bb + b) * Nn + m0) * Nn + n0;
        #pragma unroll
        for (int q = 0; q < 4; ++q)
            av[q] = *(const float4*)(ab + (size_t)arow[q] * Nn + ac4[q] * 4);
    };
    auto storeA = [&](int c) {
        uint32_t sb = sbase + (c & 1) * BUFSTRIDE;
        #pragma unroll
        for (int q = 0; q < 4; ++q) {
            uint32_t h01, l01, h23, l23;
            cvt_split(av[q].x, av[q].y, h01, l01);
            cvt_split(av[q].z, av[q].w, h23, l23);
            uint32_t so = arow[q] * (ASTR * 2) + ac4[q] * 8;
            *(uint2*)(smem + (sb - sbase) + AH_OFF + so) = make_uint2(h01, h23);
            *(uint2*)(smem + (sb - sbase) + AL_OFF + so) = make_uint2(l01, l23);
        }
    };

    issueB(0);
    loadA(0);
    storeA(0);
    for (int c = 0; c < NCH2; ++c) {
        cpa_wait0();
        __syncthreads();
        if (c + 1 < NCH2) { issueB(c + 1); loadA(c + 1); }
        mma_compute(sbase + (c & 1) * BUFSTRIDE, lane, wm, wn, acc);
        if (c + 1 < NCH2) storeA(c + 1);
    }

    // epilogue: relu + highway gate (+ bf16 plane emit for layer-1 output)
    #pragma unroll
    for (int mi = 0; mi < 4; ++mi) {
        #pragma unroll
        for (int ni = 0; ni < 4; ++ni) {
            int col = wn * 32 + ni * 8 + (lane & 3) * 2;
            #pragma unroll
            for (int h = 0; h < 2; ++h) {
                int row = m0 + wm * 64 + mi * 16 + (lane >> 2) + h * 8;
                float d0 = acc[mi][ni][h * 2 + 0];
                float d1 = acc[mi][ni][h * 2 + 1];
                size_t base = ((size_t)row * Bb + b) * Oo + col;
                float2 tv = *(const float2*)&g_t[base];
                float2 xv = *(const float2*)&X[base];
                float2 r;
                r.x = fmaxf(d0, 0.f) * tv.x + xv.x * (1.f - tv.x);
                r.y = fmaxf(d1, 0.f) * tv.y + xv.y * (1.f - tv.y);
                *(float2*)&Out[base] = r;
                if (out_to_h) {
                    uint32_t hi, lo;
                    cvt_split(r.x, r.y, hi, lo);
                    size_t moff = (size_t)(((size_t)row * Bb + b)) * Ff + col;
                    *(uint32_t*)&g_hH[moff] = hi;
                    *(uint32_t*)&g_hL[moff] = lo;
                }
            }
        }
    }
}

extern "C" void kernel_launch(void* const* d_in, const int* in_sizes, int n_in,
                              void* d_out, int out_size) {
    const float* x   = (const float*)d_in[0];
    const float* adj = (const float*)d_in[1];
    const float* W1  = (const float*)d_in[2];
    const float* b1  = (const float*)d_in[3];
    const float* Wh1 = (const float*)d_in[4];
    const float* bh1 = (const float*)d_in[5];
    const float* W2  = (const float*)d_in[6];
    const float* b2  = (const float*)d_in[7];
    const float* Wh2 = (const float*)d_in[8];
    const float* bh2 = (const float*)d_in[9];
    float* out = (float*)d_out;

    static int attr_done = 0;
    if (!attr_done) {
        cudaFuncSetAttribute(gemm1_mma, cudaFuncAttributeMaxDynamicSharedMemorySize, SMEM_TOTAL);
        cudaFuncSetAttribute(gemm2_mma, cudaFuncAttributeMaxDynamicSharedMemorySize, SMEM_TOTAL);
        attr_done = 1;
    }

    dim3 g1(Mrows / 128, 4);   // (256, 4)
    dim3 g2(Nn / 128, Bb);     // (4, 64)

    // Layer 1
    prep_weights<<<Ff * Jcols / 2 / 256, 256>>>(W1, b1, Wh1, bh1);
    x_split<<<Mrows * Ff / 4 / 256, 256>>>(x);
    gemm1_mma<<<g1, 256, SMEM_TOTAL>>>(0);
    gemm2_mma<<<g2, 256, SMEM_TOTAL>>>(adj, x, 0, nullptr, 1);   // -> g_h (+planes)
    // Layer 2
    prep_weights<<<Ff * Jcols / 2 / 256, 256>>>(W2, b2, Wh2, bh2);
    gemm1_mma<<<g1, 256, SMEM_TOTAL>>>(1);
    gemm2_mma<<<g2, 256, SMEM_TOTAL>>>(adj, nullptr, 1, out, 0); // -> d_out
}

// round 6
// speedup vs baseline: 2.4471x; 1.2490x over previous
#include <cuda_runtime.h>
#include <cuda_bf16.h>
#include <math.h>
#include <stdint.h>

// Problem constants
#define Nn 512
#define Bb 64
#define Ff 128
#define Oo 128
#define Ee 3
#define Mrows (Nn*Bb)     // 32768
#define Jcols 512         // 3*O + O(highway)

// Scratch (static device globals)
__device__ float g_t[(size_t)Mrows*Oo];          // sigmoid gate [m, o]
__device__ float g_h[(size_t)Mrows*Oo];          // layer-1 output fp32 (highway X)
__device__ float g_bcat[Jcols];
__device__ __nv_bfloat16 g_WcatH[Ff*Jcols];
__device__ __nv_bfloat16 g_WcatL[Ff*Jcols];
__device__ __nv_bfloat16 g_xH[(size_t)Mrows*Ff];  // layer-1 X planes
__device__ __nv_bfloat16 g_xL[(size_t)Mrows*Ff];
__device__ __nv_bfloat16 g_hH[(size_t)Mrows*Ff];  // layer-2 X planes
__device__ __nv_bfloat16 g_hL[(size_t)Mrows*Ff];
// support planes [e,b,n,o]
__device__ __nv_bfloat16 g_supH[(size_t)Ee*Bb*Nn*Oo];
__device__ __nv_bfloat16 g_supL[(size_t)Ee*Bb*Nn*Oo];

// ---- bf16 split: (x,y) -> packed hi pair + packed lo pair ----
__device__ __forceinline__ void cvt_split(float x, float y, uint32_t& hi, uint32_t& lo) {
    __nv_bfloat162 h = __floats2bfloat162_rn(x, y);
    float2 hf = __bfloat1622float2(h);
    __nv_bfloat162 l = __floats2bfloat162_rn(x - hf.x, y - hf.y);
    hi = *reinterpret_cast<uint32_t*>(&h);
    lo = *reinterpret_cast<uint32_t*>(&l);
}

__device__ __forceinline__ uint32_t smem_u32(const void* p) {
    uint32_t a;
    asm("{ .reg .u64 t; cvta.to.shared.u64 t, %1; cvt.u32.u64 %0, t; }" : "=r"(a) : "l"(p));
    return a;
}

// ---- cp.async ----
__device__ __forceinline__ void cpa16(uint32_t saddr, const void* g) {
    asm volatile("cp.async.cg.shared.global [%0], [%1], 16;" :: "r"(saddr), "l"(g));
}
__device__ __forceinline__ void cpa_commit() {
    asm volatile("cp.async.commit_group;" ::: "memory");
}
__device__ __forceinline__ void cpa_wait0() {
    asm volatile("cp.async.wait_group 0;" ::: "memory");
}

// ---- warp-level MMA primitives ----
__device__ __forceinline__ void ldsm4(uint32_t r[4], uint32_t addr) {
    asm volatile("ldmatrix.sync.aligned.m8n8.x4.shared.b16 {%0,%1,%2,%3}, [%4];"
                 : "=r"(r[0]), "=r"(r[1]), "=r"(r[2]), "=r"(r[3]) : "r"(addr));
}
__device__ __forceinline__ void ldsm4t(uint32_t r[4], uint32_t addr) {
    asm volatile("ldmatrix.sync.aligned.m8n8.x4.trans.shared.b16 {%0,%1,%2,%3}, [%4];"
                 : "=r"(r[0]), "=r"(r[1]), "=r"(r[2]), "=r"(r[3]) : "r"(addr));
}
__device__ __forceinline__ void mma16816(float c[4], const uint32_t a[4], const uint32_t b[2]) {
    asm volatile(
        "mma.sync.aligned.m16n8k16.row.col.f32.bf16.bf16.f32 "
        "{%0,%1,%2,%3}, {%4,%5,%6,%7}, {%8,%9}, {%0,%1,%2,%3};"
        : "+f"(c[0]), "+f"(c[1]), "+f"(c[2]), "+f"(c[3])
        : "r"(a[0]), "r"(a[1]), "r"(a[2]), "r"(a[3]), "r"(b[0]), "r"(b[1]));
}

// ---- shared tile geometry (both GEMMs) ----
#define ASTR 40       // A smem row stride (bf16 elems), 80 B
#define BSTR 136      // B smem row stride (bf16 elems), 272 B
#define A_PLANE 10240 // 128*40*2 bytes
#define B_PLANE 8704  // 32*136*2 bytes
#define AH_OFF 0
#define AL_OFF A_PLANE
#define BH_OFF (2*A_PLANE)
#define BL_OFF (2*A_PLANE + B_PLANE)
#define BUFSTRIDE (2*A_PLANE + 2*B_PLANE)   // 37888
#define SMEM_TOTAL (2*BUFSTRIDE)            // 75776

// 3-pass MMA compute on one staged buffer. 2x4 warp grid, 64x32 warp tiles.
// Register-pressure-ordered: HH and HL first (ah/bh/bl live), then load al for LH.
__device__ __forceinline__ void mma_compute(uint32_t sb, int lane, int wm, int wn,
                                            float acc[4][4][4]) {
    #pragma unroll
    for (int ks = 0; ks < 2; ++ks) {
        int k0 = ks * 16;
        uint32_t abase = sb + ((wm * 64 + (lane & 15)) * ASTR + k0 + ((lane >> 4) << 3)) * 2;
        uint32_t bbase = sb + ((k0 + (lane & 15)) * BSTR + wn * 32 + ((lane >> 4) << 3)) * 2;

        uint32_t ah[4][4], bhf[4][2], blf[4][2];
        #pragma unroll
        for (int mi = 0; mi < 4; ++mi)
            ldsm4(ah[mi], abase + AH_OFF + mi * 16 * ASTR * 2);
        #pragma unroll
        for (int g = 0; g < 2; ++g) {
            uint32_t r[4];
            ldsm4t(r, bbase + BH_OFF + g * 32);
            bhf[g*2][0] = r[0]; bhf[g*2][1] = r[1];
            bhf[g*2+1][0] = r[2]; bhf[g*2+1][1] = r[3];
            ldsm4t(r, bbase + BL_OFF + g * 32);
            blf[g*2][0] = r[0]; blf[g*2][1] = r[1];
            blf[g*2+1][0] = r[2]; blf[g*2+1][1] = r[3];
        }
        #pragma unroll
        for (int mi = 0; mi < 4; ++mi)
            #pragma unroll
            for (int ni = 0; ni < 4; ++ni) {
                mma16816(acc[mi][ni], ah[mi], bhf[ni]);   // HH
                mma16816(acc[mi][ni], ah[mi], blf[ni]);   // HL
            }
        // LH pass: reuse ah register space for al
        uint32_t al[4][4];
        #pragma unroll
        for (int mi = 0; mi < 4; ++mi)
            ldsm4(al[mi], abase + AL_OFF + mi * 16 * ASTR * 2);
        #pragma unroll
        for (int mi = 0; mi < 4; ++mi)
            #pragma unroll
            for (int ni = 0; ni < 4; ++ni)
                mma16816(acc[mi][ni], al[mi], bhf[ni]);   // LH
    }
}

// ---------------------------------------------------------------------------
// prep_weights: W/Wh -> bf16 hi/lo planes [f][j], biases fp32
// ---------------------------------------------------------------------------
__global__ void prep_weights(const float* __restrict__ W, const float* __restrict__ b,
                             const float* __restrict__ Wh, const float* __restrict__ bh) {
    int idx = blockIdx.x * blockDim.x + threadIdx.x;   // over Ff*Jcols/2 pairs
    if (idx < Ff * Jcols / 2) {
        int f = idx / (Jcols / 2), jp = idx % (Jcols / 2);
        int j = jp * 2;
        float v0, v1;
        if (j < 3 * Oo) {
            int e = j >> 7, o = j & 127;
            v0 = W[((size_t)e * Ff + f) * Oo + o];
            v1 = W[((size_t)e * Ff + f) * Oo + o + 1];
        } else {
            v0 = Wh[(size_t)f * Oo + (j - 3 * Oo)];
            v1 = Wh[(size_t)f * Oo + (j - 3 * Oo) + 1];
        }
        uint32_t hi, lo;
        cvt_split(v0, v1, hi, lo);
        *(uint32_t*)&g_WcatH[f * Jcols + j] = hi;
        *(uint32_t*)&g_WcatL[f * Jcols + j] = lo;
    }
    if (idx < Jcols) {
        int j = idx;
        g_bcat[j] = (j < 3 * Oo) ? b[(j >> 7) * Oo + (j & 127)] : bh[j - 3 * Oo];
    }
}

// ---------------------------------------------------------------------------
// x_split: fp32 [m,f] -> bf16 hi/lo planes (layer-1 X)
// ---------------------------------------------------------------------------
__global__ void x_split(const float* __restrict__ x) {
    int i = blockIdx.x * blockDim.x + threadIdx.x;   // over float4 slots
    float4 v = ((const float4*)x)[i];
    uint32_t h01, l01, h23, l23;
    cvt_split(v.x, v.y, h01, l01);
    cvt_split(v.z, v.w, h23, l23);
    ((uint2*)g_xH)[i] = make_uint2(h01, h23);
    ((uint2*)g_xL)[i] = make_uint2(l01, l23);
}

// ---------------------------------------------------------------------------
// GEMM1 on mma.sync: C[m, j] = X[m,:] @ Wcat[:, jb*128..] + bias
// grid (Mrows/128, 4). A and B via cp.async (all bf16 in gmem). NCH=4.
// ---------------------------------------------------------------------------
__global__ __launch_bounds__(256, 2) void gemm1_mma(int x_from_h) {
    extern __shared__ char smem[];
    const __nv_bfloat16* __restrict__ XH = x_from_h ? g_hH : g_xH;
    const __nv_bfloat16* __restrict__ XL = x_from_h ? g_hL : g_xL;
    uint32_t sbase = smem_u32(smem);

    int tid = threadIdx.x, lane = tid & 31, wid = tid >> 5;
    int wm = wid & 1, wn = wid >> 1;
    int m0 = blockIdx.x * 128, jb = blockIdx.y;

    float acc[4][4][4];
    #pragma unroll
    for (int mi = 0; mi < 4; ++mi)
        #pragma unroll
        for (int ni = 0; ni < 4; ++ni)
            #pragma unroll
            for (int r = 0; r < 4; ++r) acc[mi][ni][r] = 0.f;

    auto issue = [&](int c) {
        uint32_t sb = sbase + (c & 1) * BUFSTRIDE;
        int k0 = c * 32;
        #pragma unroll
        for (int q = 0; q < 2; ++q) {           // A: 128 rows x 32 k, 4 uint4/row
            int i = q * 256 + tid;
            int row = i >> 2, c8 = i & 3;
            uint32_t so = row * (ASTR * 2) + c8 * 16;
            size_t go = (size_t)(m0 + row) * Ff + k0 + c8 * 8;
            cpa16(sb + AH_OFF + so, XH + go);
            cpa16(sb + AL_OFF + so, XL + go);
        }
        #pragma unroll
        for (int q = 0; q < 2; ++q) {           // B: 32 rows x 128 cols
            int i = q * 256 + tid;
            int row = i >> 4, c8 = i & 15;
            uint32_t so = row * (BSTR * 2) + c8 * 16;
            size_t go = (size_t)(k0 + row) * Jcols + jb * 128 + c8 * 8;
            cpa16(sb + BH_OFF + so, g_WcatH + go);
            cpa16(sb + BL_OFF + so, g_WcatL + go);
        }
        cpa_commit();
    };

    issue(0);
    #pragma unroll
    for (int c = 0; c < 4; ++c) {
        cpa_wait0();
        __syncthreads();
        if (c + 1 < 4) issue(c + 1);
        mma_compute(sbase + (c & 1) * BUFSTRIDE, lane, wm, wn, acc);
        if (c + 1 < 4) __syncthreads();
    }

    // epilogue: add bias; jb<3 -> split to sup planes; jb==3 -> sigmoid -> g_t
    #pragma unroll
    for (int mi = 0; mi < 4; ++mi) {
        #pragma unroll
        for (int ni = 0; ni < 4; ++ni) {
            int col = wn * 32 + ni * 8 + (lane & 3) * 2;
            float bb0 = g_bcat[jb * 128 + col], bb1 = g_bcat[jb * 128 + col + 1];
            #pragma unroll
            for (int h = 0; h < 2; ++h) {
                int m = m0 + wm * 64 + mi * 16 + (lane >> 2) + h * 8;
                float d0 = acc[mi][ni][h * 2 + 0] + bb0;
                float d1 = acc[mi][ni][h * 2 + 1] + bb1;
                if (jb < 3) {
                    int n = m >> 6, bidx = m & 63;
                    uint32_t hi, lo;
                    cvt_split(d0, d1, hi, lo);
                    size_t off = (((size_t)jb * Bb + bidx) * Nn + n) * Oo + col;
                    *(uint32_t*)&g_supH[off] = hi;
                    *(uint32_t*)&g_supL[off] = lo;
                } else {
                    float2 r;
                    r.x = 1.f / (1.f + expf(-d0));
                    r.y = 1.f / (1.f + expf(-d1));
                    *(float2*)&g_t[(size_t)m * Oo + col] = r;
                }
            }
        }
    }
}

// ---------------------------------------------------------------------------
// GEMM2 on mma.sync: out[m,b,:] = relu(sum adj*sup) highway-gated
// grid (4, 64). B via cp.async; A (adj fp32) register-staged + cvt. NCH=48.
// ---------------------------------------------------------------------------
#define NCH2 48

__global__ __launch_bounds__(256, 2) void gemm2_mma(const float* __restrict__ adj,
                                                    const float* __restrict__ Xin, int x_from_h,
                                                    float* __restrict__ OutExt, int out_to_h) {
    extern __shared__ char smem[];
    const float* __restrict__ X = x_from_h ? g_h : Xin;
    float* __restrict__ Out = out_to_h ? g_h : OutExt;
    uint32_t sbase = smem_u32(smem);

    int tid = threadIdx.x, lane = tid & 31, wid = tid >> 5;
    int wm = wid & 1, wn = wid >> 1;
    int m0 = blockIdx.x * 128, b = blockIdx.y;

    float acc[4][4][4];
    #pragma unroll
    for (int mi = 0; mi < 4; ++mi)
        #pragma unroll
        for (int ni = 0; ni < 4; ++ni)
            #pragma unroll
            for (int r = 0; r < 4; ++r) acc[mi][ni][r] = 0.f;

    int arow[4], ac4[4];
    #pragma unroll
    for (int q = 0; q < 4; ++q) { int i = q * 256 + tid; arow[q] = i >> 3; ac4[q] = i & 7; }
    float4 av[4];

    auto issueB = [&](int c) {
        uint32_t sb = sbase + (c & 1) * BUFSTRIDE;
        int e = c >> 4, n0 = (c & 15) * 32;
        size_t gb = (((size_t)e * Bb + b) * Nn + n0) * Oo;
        #pragma unroll
        for (int q = 0; q < 2; ++q) {
            int i = q * 256 + tid;
            int row = i >> 4, c8 = i & 15;
            uint32_t so = row * (BSTR * 2) + c8 * 16;
            size_t go = gb + (size_t)row * Oo + c8 * 8;
            cpa16(sb + BH_OFF + so, g_supH + go);
            cpa16(sb + BL_OFF + so, g_supL + go);
        }
        cpa_commit();
    };
    auto loadA = [&](int c) {
        int e = c >> 4, n0 = (c & 15) * 32;
        const float* ab = adj + (((size_t)e * Bb + b) * Nn + m0) * Nn + n0;
        #pragma unroll
        for (int q = 0; q < 4; ++q)
            av[q] = *(const float4*)(ab + (size_t)arow[q] * Nn + ac4[q] * 4);
    };
    auto storeA = [&](int c) {
        uint32_t off = (c & 1) * BUFSTRIDE;
        #pragma unroll
        for (int q = 0; q < 4; ++q) {
            uint32_t h01, l01, h23, l23;
            cvt_split(av[q].x, av[q].y, h01, l01);
            cvt_split(av[q].z, av[q].w, h23, l23);
            uint32_t so = arow[q] * (ASTR * 2) + ac4[q] * 8;
            *(uint2*)(smem + off + AH_OFF + so) = make_uint2(h01, h23);
            *(uint2*)(smem + off + AL_OFF + so) = make_uint2(l01, l23);
        }
    };

    issueB(0);
    loadA(0);
    storeA(0);
    for (int c = 0; c < NCH2; ++c) {
        cpa_wait0();
        __syncthreads();
        if (c + 1 < NCH2) { issueB(c + 1); loadA(c + 1); }
        mma_compute(sbase + (c & 1) * BUFSTRIDE, lane, wm, wn, acc);
        if (c + 1 < NCH2) storeA(c + 1);
    }

    // epilogue: relu + highway gate (+ bf16 plane emit for layer-1 output)
    #pragma unroll
    for (int mi = 0; mi < 4; ++mi) {
        #pragma unroll
        for (int ni = 0; ni < 4; ++ni) {
            int col = wn * 32 + ni * 8 + (lane & 3) * 2;
            #pragma unroll
            for (int h = 0; h < 2; ++h) {
                int row = m0 + wm * 64 + mi * 16 + (lane >> 2) + h * 8;
                float d0 = acc[mi][ni][h * 2 + 0];
                float d1 = acc[mi][ni][h * 2 + 1];
                size_t base = ((size_t)row * Bb + b) * Oo + col;
                float2 tv = *(const float2*)&g_t[base];
                float2 xv = *(const float2*)&X[base];
                float2 r;
                r.x = fmaxf(d0, 0.f) * tv.x + xv.x * (1.f - tv.x);
                r.y = fmaxf(d1, 0.f) * tv.y + xv.y * (1.f - tv.y);
                *(float2*)&Out[base] = r;
                if (out_to_h) {
                    uint32_t hi, lo;
                    cvt_split(r.x, r.y, hi, lo);
                    size_t moff = (size_t)(((size_t)row * Bb + b)) * Ff + col;
                    *(uint32_t*)&g_hH[moff] = hi;
                    *(uint32_t*)&g_hL[moff] = lo;
                }
            }
        }
    }
}

extern "C" void kernel_launch(void* const* d_in, const int* in_sizes, int n_in,
                              void* d_out, int out_size) {
    const float* x   = (const float*)d_in[0];
    const float* adj = (const float*)d_in[1];
    const float* W1  = (const float*)d_in[2];
    const float* b1  = (const float*)d_in[3];
    const float* Wh1 = (const float*)d_in[4];
    const float* bh1 = (const float*)d_in[5];
    const float* W2  = (const float*)d_in[6];
    const float* b2  = (const float*)d_in[7];
    const float* Wh2 = (const float*)d_in[8];
    const float* bh2 = (const float*)d_in[9];
    float* out = (float*)d_out;

    static int attr_done = 0;
    if (!attr_done) {
        cudaFuncSetAttribute(gemm1_mma, cudaFuncAttributeMaxDynamicSharedMemorySize, SMEM_TOTAL);
        cudaFuncSetAttribute(gemm2_mma, cudaFuncAttributeMaxDynamicSharedMemorySize, SMEM_TOTAL);
        attr_done = 1;
    }

    dim3 g1(Mrows / 128, 4);   // (256, 4)
    dim3 g2(Nn / 128, Bb);     // (4, 64)

    // Layer 1
    prep_weights<<<Ff * Jcols / 2 / 256, 256>>>(W1, b1, Wh1, bh1);
    x_split<<<Mrows * Ff / 4 / 256, 256>>>(x);
    gemm1_mma<<<g1, 256, SMEM_TOTAL>>>(0);
    gemm2_mma<<<g2, 256, SMEM_TOTAL>>>(adj, x, 0, nullptr, 1);   // -> g_h (+planes)
    // Layer 2
    prep_weights<<<Ff * Jcols / 2 / 256, 256>>>(W2, b2, Wh2, bh2);
    gemm1_mma<<<g1, 256, SMEM_TOTAL>>>(1);
    gemm2_mma<<<g2, 256, SMEM_TOTAL>>>(adj, nullptr, 1, out, 0); // -> d_out
}

// round 7
// speedup vs baseline: 3.0556x; 1.2486x over previous
#include <cuda_runtime.h>
#include <cuda_fp16.h>
#include <math.h>
#include <stdint.h>

// Problem constants
#define Nn 512
#define Bb 64
#define Ff 128
#define Oo 128
#define Ee 3
#define Mrows (Nn*Bb)     // 32768
#define Jcols 512         // 3*O + O(highway)

// Scratch (static device globals)
__device__ float g_t[(size_t)Mrows*Oo];          // sigmoid gate [m, o]
__device__ float g_h[(size_t)Mrows*Oo];          // layer-1 output fp32 (highway X)
__device__ float g_bcat[Jcols];
__device__ __half g_WcatH[Ff*Jcols];
__device__ __half g_WcatL[Ff*Jcols];
__device__ __half g_xH[(size_t)Mrows*Ff];  // layer-1 X planes
__device__ __half g_xL[(size_t)Mrows*Ff];
__device__ __half g_hH[(size_t)Mrows*Ff];  // layer-2 X planes
__device__ __half g_hL[(size_t)Mrows*Ff];
// support fp16 (single plane) [e,b,n,o]
__device__ __half g_supH[(size_t)Ee*Bb*Nn*Oo];

// ---- fp16 split: (x,y) -> packed hi pair + packed lo pair ----
__device__ __forceinline__ void cvt_split16(float x, float y, uint32_t& hi, uint32_t& lo) {
    __half2 h = __floats2half2_rn(x, y);
    float2 hf = __half22float2(h);
    __half2 l = __floats2half2_rn(x - hf.x, y - hf.y);
    hi = *reinterpret_cast<uint32_t*>(&h);
    lo = *reinterpret_cast<uint32_t*>(&l);
}
__device__ __forceinline__ uint32_t cvt16(float x, float y) {
    __half2 h = __floats2half2_rn(x, y);
    return *reinterpret_cast<uint32_t*>(&h);
}

__device__ __forceinline__ uint32_t smem_u32(const void* p) {
    uint32_t a;
    asm("{ .reg .u64 t; cvta.to.shared.u64 t, %1; cvt.u32.u64 %0, t; }" : "=r"(a) : "l"(p));
    return a;
}

// ---- cp.async ----
__device__ __forceinline__ void cpa16(uint32_t saddr, const void* g) {
    asm volatile("cp.async.cg.shared.global [%0], [%1], 16;" :: "r"(saddr), "l"(g));
}
__device__ __forceinline__ void cpa_commit() {
    asm volatile("cp.async.commit_group;" ::: "memory");
}
__device__ __forceinline__ void cpa_wait0() {
    asm volatile("cp.async.wait_group 0;" ::: "memory");
}

// ---- warp-level MMA primitives (fp16 in, fp32 accum) ----
__device__ __forceinline__ void ldsm4(uint32_t r[4], uint32_t addr) {
    asm volatile("ldmatrix.sync.aligned.m8n8.x4.shared.b16 {%0,%1,%2,%3}, [%4];"
                 : "=r"(r[0]), "=r"(r[1]), "=r"(r[2]), "=r"(r[3]) : "r"(addr));
}
__device__ __forceinline__ void ldsm4t(uint32_t r[4], uint32_t addr) {
    asm volatile("ldmatrix.sync.aligned.m8n8.x4.trans.shared.b16 {%0,%1,%2,%3}, [%4];"
                 : "=r"(r[0]), "=r"(r[1]), "=r"(r[2]), "=r"(r[3]) : "r"(addr));
}
__device__ __forceinline__ void mma16816(float c[4], const uint32_t a[4], const uint32_t b[2]) {
    asm volatile(
        "mma.sync.aligned.m16n8k16.row.col.f32.f16.f16.f32 "
        "{%0,%1,%2,%3}, {%4,%5,%6,%7}, {%8,%9}, {%0,%1,%2,%3};"
        : "+f"(c[0]), "+f"(c[1]), "+f"(c[2]), "+f"(c[3])
        : "r"(a[0]), "r"(a[1]), "r"(a[2]), "r"(a[3]), "r"(b[0]), "r"(b[1]));
}

// ---- shared tile geometry ----
#define ASTR 40       // A smem row stride (half elems), 80 B
#define BSTR 136      // B smem row stride (half elems), 272 B
#define A_PLANE 10240 // 128*40*2 bytes
#define B_PLANE 8704  // 32*136*2 bytes
#define AH_OFF 0
#define AL_OFF A_PLANE
#define BH_OFF (2*A_PLANE)
#define BL_OFF (2*A_PLANE + B_PLANE)
// gemm1: A hi/lo + B hi/lo
#define BUFSTRIDE1 (2*A_PLANE + 2*B_PLANE)  // 37888
#define SMEM1_TOTAL (2*BUFSTRIDE1)          // 75776
// gemm2: A hi/lo + B hi only
#define BUFSTRIDE2 (2*A_PLANE + B_PLANE)    // 29184
#define SMEM2_TOTAL (2*BUFSTRIDE2)          // 58368

// 3-pass compute (gemm1): HH + HL + LH
__device__ __forceinline__ void mma_compute3(uint32_t sb, int lane, int wm, int wn,
                                             float acc[4][4][4]) {
    #pragma unroll
    for (int ks = 0; ks < 2; ++ks) {
        int k0 = ks * 16;
        uint32_t abase = sb + ((wm * 64 + (lane & 15)) * ASTR + k0 + ((lane >> 4) << 3)) * 2;
        uint32_t bbase = sb + ((k0 + (lane & 15)) * BSTR + wn * 32 + ((lane >> 4) << 3)) * 2;

        uint32_t ah[4][4], bhf[4][2], blf[4][2];
        #pragma unroll
        for (int mi = 0; mi < 4; ++mi)
            ldsm4(ah[mi], abase + AH_OFF + mi * 16 * ASTR * 2);
        #pragma unroll
        for (int g = 0; g < 2; ++g) {
            uint32_t r[4];
            ldsm4t(r, bbase + BH_OFF + g * 32);
            bhf[g*2][0] = r[0]; bhf[g*2][1] = r[1];
            bhf[g*2+1][0] = r[2]; bhf[g*2+1][1] = r[3];
            ldsm4t(r, bbase + BL_OFF + g * 32);
            blf[g*2][0] = r[0]; blf[g*2][1] = r[1];
            blf[g*2+1][0] = r[2]; blf[g*2+1][1] = r[3];
        }
        #pragma unroll
        for (int mi = 0; mi < 4; ++mi)
            #pragma unroll
            for (int ni = 0; ni < 4; ++ni) {
                mma16816(acc[mi][ni], ah[mi], bhf[ni]);   // HH
                mma16816(acc[mi][ni], ah[mi], blf[ni]);   // HL
            }
        uint32_t al[4][4];
        #pragma unroll
        for (int mi = 0; mi < 4; ++mi)
            ldsm4(al[mi], abase + AL_OFF + mi * 16 * ASTR * 2);
        #pragma unroll
        for (int mi = 0; mi < 4; ++mi)
            #pragma unroll
            for (int ni = 0; ni < 4; ++ni)
                mma16816(acc[mi][ni], al[mi], bhf[ni]);   // LH
    }
}

// 2-pass compute (gemm2): (ah + al) * bh
__device__ __forceinline__ void mma_compute2(uint32_t sb, int lane, int wm, int wn,
                                             float acc[4][4][4]) {
    #pragma unroll
    for (int ks = 0; ks < 2; ++ks) {
        int k0 = ks * 16;
        uint32_t abase = sb + ((wm * 64 + (lane & 15)) * ASTR + k0 + ((lane >> 4) << 3)) * 2;
        uint32_t bbase = sb + ((k0 + (lane & 15)) * BSTR + wn * 32 + ((lane >> 4) << 3)) * 2;

        uint32_t ah[4][4], bhf[4][2];
        #pragma unroll
        for (int mi = 0; mi < 4; ++mi)
            ldsm4(ah[mi], abase + AH_OFF + mi * 16 * ASTR * 2);
        #pragma unroll
        for (int g = 0; g < 2; ++g) {
            uint32_t r[4];
            ldsm4t(r, bbase + BH_OFF + g * 32);
            bhf[g*2][0] = r[0]; bhf[g*2][1] = r[1];
            bhf[g*2+1][0] = r[2]; bhf[g*2+1][1] = r[3];
        }
        #pragma unroll
        for (int mi = 0; mi < 4; ++mi)
            #pragma unroll
            for (int ni = 0; ni < 4; ++ni)
                mma16816(acc[mi][ni], ah[mi], bhf[ni]);   // HH
        uint32_t al[4][4];
        #pragma unroll
        for (int mi = 0; mi < 4; ++mi)
            ldsm4(al[mi], abase + AL_OFF + mi * 16 * ASTR * 2);
        #pragma unroll
        for (int mi = 0; mi < 4; ++mi)
            #pragma unroll
            for (int ni = 0; ni < 4; ++ni)
                mma16816(acc[mi][ni], al[mi], bhf[ni]);   // LH
    }
}

// ---------------------------------------------------------------------------
// prep_weights: W/Wh -> fp16 hi/lo planes [f][j], biases fp32
// ---------------------------------------------------------------------------
__global__ void prep_weights(const float* __restrict__ W, const float* __restrict__ b,
                             const float* __restrict__ Wh, const float* __restrict__ bh) {
    int idx = blockIdx.x * blockDim.x + threadIdx.x;   // over Ff*Jcols/2 pairs
    if (idx < Ff * Jcols / 2) {
        int f = idx / (Jcols / 2), jp = idx % (Jcols / 2);
        int j = jp * 2;
        float v0, v1;
        if (j < 3 * Oo) {
            int e = j >> 7, o = j & 127;
            v0 = W[((size_t)e * Ff + f) * Oo + o];
            v1 = W[((size_t)e * Ff + f) * Oo + o + 1];
        } else {
            v0 = Wh[(size_t)f * Oo + (j - 3 * Oo)];
            v1 = Wh[(size_t)f * Oo + (j - 3 * Oo) + 1];
        }
        uint32_t hi, lo;
        cvt_split16(v0, v1, hi, lo);
        *(uint32_t*)&g_WcatH[f * Jcols + j] = hi;
        *(uint32_t*)&g_WcatL[f * Jcols + j] = lo;
    }
    if (idx < Jcols) {
        int j = idx;
        g_bcat[j] = (j < 3 * Oo) ? b[(j >> 7) * Oo + (j & 127)] : bh[j - 3 * Oo];
    }
}

// ---------------------------------------------------------------------------
// x_split: fp32 [m,f] -> fp16 hi/lo planes (layer-1 X)
// ---------------------------------------------------------------------------
__global__ void x_split(const float* __restrict__ x) {
    int i = blockIdx.x * blockDim.x + threadIdx.x;   // over float4 slots
    float4 v = ((const float4*)x)[i];
    uint32_t h01, l01, h23, l23;
    cvt_split16(v.x, v.y, h01, l01);
    cvt_split16(v.z, v.w, h23, l23);
    ((uint2*)g_xH)[i] = make_uint2(h01, h23);
    ((uint2*)g_xL)[i] = make_uint2(l01, l23);
}

// ---------------------------------------------------------------------------
// GEMM1 on mma.sync (fp16 3-pass): C[m, j] = X[m,:] @ Wcat[:, jb*128..] + bias
// grid (Mrows/128, 4). NCH=4.
// ---------------------------------------------------------------------------
__global__ __launch_bounds__(256, 2) void gemm1_mma(int x_from_h) {
    extern __shared__ char smem[];
    const __half* __restrict__ XH = x_from_h ? g_hH : g_xH;
    const __half* __restrict__ XL = x_from_h ? g_hL : g_xL;
    uint32_t sbase = smem_u32(smem);

    int tid = threadIdx.x, lane = tid & 31, wid = tid >> 5;
    int wm = wid & 1, wn = wid >> 1;
    int m0 = blockIdx.x * 128, jb = blockIdx.y;

    float acc[4][4][4];
    #pragma unroll
    for (int mi = 0; mi < 4; ++mi)
        #pragma unroll
        for (int ni = 0; ni < 4; ++ni)
            #pragma unroll
            for (int r = 0; r < 4; ++r) acc[mi][ni][r] = 0.f;

    auto issue = [&](int c) {
        uint32_t sb = sbase + (c & 1) * BUFSTRIDE1;
        int k0 = c * 32;
        #pragma unroll
        for (int q = 0; q < 2; ++q) {           // A: 128 rows x 32 k
            int i = q * 256 + tid;
            int row = i >> 2, c8 = i & 3;
            uint32_t so = row * (ASTR * 2) + c8 * 16;
            size_t go = (size_t)(m0 + row) * Ff + k0 + c8 * 8;
            cpa16(sb + AH_OFF + so, XH + go);
            cpa16(sb + AL_OFF + so, XL + go);
        }
        #pragma unroll
        for (int q = 0; q < 2; ++q) {           // B: 32 rows x 128 cols
            int i = q * 256 + tid;
            int row = i >> 4, c8 = i & 15;
            uint32_t so = row * (BSTR * 2) + c8 * 16;
            size_t go = (size_t)(k0 + row) * Jcols + jb * 128 + c8 * 8;
            cpa16(sb + BH_OFF + so, g_WcatH + go);
            cpa16(sb + BL_OFF + so, g_WcatL + go);
        }
        cpa_commit();
    };

    issue(0);
    #pragma unroll
    for (int c = 0; c < 4; ++c) {
        cpa_wait0();
        __syncthreads();
        if (c + 1 < 4) issue(c + 1);
        mma_compute3(sbase + (c & 1) * BUFSTRIDE1, lane, wm, wn, acc);
        if (c + 1 < 4) __syncthreads();
    }

    // epilogue: add bias; jb<3 -> fp16 support; jb==3 -> sigmoid -> g_t
    #pragma unroll
    for (int mi = 0; mi < 4; ++mi) {
        #pragma unroll
        for (int ni = 0; ni < 4; ++ni) {
            int col = wn * 32 + ni * 8 + (lane & 3) * 2;
            float bb0 = g_bcat[jb * 128 + col], bb1 = g_bcat[jb * 128 + col + 1];
            #pragma unroll
            for (int h = 0; h < 2; ++h) {
                int m = m0 + wm * 64 + mi * 16 + (lane >> 2) + h * 8;
                float d0 = acc[mi][ni][h * 2 + 0] + bb0;
                float d1 = acc[mi][ni][h * 2 + 1] + bb1;
                if (jb < 3) {
                    int n = m >> 6, bidx = m & 63;
                    size_t off = (((size_t)jb * Bb + bidx) * Nn + n) * Oo + col;
                    *(uint32_t*)&g_supH[off] = cvt16(d0, d1);
                } else {
                    float2 r;
                    r.x = 1.f / (1.f + expf(-d0));
                    r.y = 1.f / (1.f + expf(-d1));
                    *(float2*)&g_t[(size_t)m * Oo + col] = r;
                }
            }
        }
    }
}

// ---------------------------------------------------------------------------
// GEMM2 on mma.sync (fp16 2-pass): out[m,b,:] = relu(sum adj*sup) gated
// grid (4, 64). B (supH) via cp.async; A (adj fp32) register-staged + split.
// ---------------------------------------------------------------------------
#define NCH2 48

__global__ __launch_bounds__(256, 2) void gemm2_mma(const float* __restrict__ adj,
                                                    const float* __restrict__ Xin, int x_from_h,
                                                    float* __restrict__ OutExt, int out_to_h) {
    extern __shared__ char smem[];
    const float* __restrict__ X = x_from_h ? g_h : Xin;
    float* __restrict__ Out = out_to_h ? g_h : OutExt;
    uint32_t sbase = smem_u32(smem);

    int tid = threadIdx.x, lane = tid & 31, wid = tid >> 5;
    int wm = wid & 1, wn = wid >> 1;
    int m0 = blockIdx.x * 128, b = blockIdx.y;

    float acc[4][4][4];
    #pragma unroll
    for (int mi = 0; mi < 4; ++mi)
        #pragma unroll
        for (int ni = 0; ni < 4; ++ni)
            #pragma unroll
            for (int r = 0; r < 4; ++r) acc[mi][ni][r] = 0.f;

    int arow[4], ac4[4];
    #pragma unroll
    for (int q = 0; q < 4; ++q) { int i = q * 256 + tid; arow[q] = i >> 3; ac4[q] = i & 7; }
    float4 av[4];

    auto issueB = [&](int c) {
        uint32_t sb = sbase + (c & 1) * BUFSTRIDE2;
        int e = c >> 4, n0 = (c & 15) * 32;
        size_t gb = (((size_t)e * Bb + b) * Nn + n0) * Oo;
        #pragma unroll
        for (int q = 0; q < 2; ++q) {
            int i = q * 256 + tid;
            int row = i >> 4, c8 = i & 15;
            uint32_t so = row * (BSTR * 2) + c8 * 16;
            cpa16(sb + BH_OFF + so, g_supH + gb + (size_t)row * Oo + c8 * 8);
        }
        cpa_commit();
    };
    auto loadA = [&](int c) {
        int e = c >> 4, n0 = (c & 15) * 32;
        const float* ab = adj + (((size_t)e * Bb + b) * Nn + m0) * Nn + n0;
        #pragma unroll
        for (int q = 0; q < 4; ++q)
            av[q] = *(const float4*)(ab + (size_t)arow[q] * Nn + ac4[q] * 4);
    };
    auto storeA = [&](int c) {
        uint32_t off = (c & 1) * BUFSTRIDE2;
        #pragma unroll
        for (int q = 0; q < 4; ++q) {
            uint32_t h01, l01, h23, l23;
            cvt_split16(av[q].x, av[q].y, h01, l01);
            cvt_split16(av[q].z, av[q].w, h23, l23);
            uint32_t so = arow[q] * (ASTR * 2) + ac4[q] * 8;
            *(uint2*)(smem + off + AH_OFF + so) = make_uint2(h01, h23);
            *(uint2*)(smem + off + AL_OFF + so) = make_uint2(l01, l23);
        }
    };

    issueB(0);
    loadA(0);
    storeA(0);
    for (int c = 0; c < NCH2; ++c) {
        cpa_wait0();
        __syncthreads();
        if (c + 1 < NCH2) { issueB(c + 1); loadA(c + 1); }
        mma_compute2(sbase + (c & 1) * BUFSTRIDE2, lane, wm, wn, acc);
        if (c + 1 < NCH2) storeA(c + 1);
    }

    // epilogue: relu + highway gate (+ fp16 plane emit for layer-1 output)
    #pragma unroll
    for (int mi = 0; mi < 4; ++mi) {
        #pragma unroll
        for (int ni = 0; ni < 4; ++ni) {
            int col = wn * 32 + ni * 8 + (lane & 3) * 2;
            #pragma unroll
            for (int h = 0; h < 2; ++h) {
                int row = m0 + wm * 64 + mi * 16 + (lane >> 2) + h * 8;
                float d0 = acc[mi][ni][h * 2 + 0];
                float d1 = acc[mi][ni][h * 2 + 1];
                size_t base = ((size_t)row * Bb + b) * Oo + col;
                float2 tv = *(const float2*)&g_t[base];
                float2 xv = *(const float2*)&X[base];
                float2 r;
                r.x = fmaxf(d0, 0.f) * tv.x + xv.x * (1.f - tv.x);
                r.y = fmaxf(d1, 0.f) * tv.y + xv.y * (1.f - tv.y);
                *(float2*)&Out[base] = r;
                if (out_to_h) {
                    uint32_t hi, lo;
                    cvt_split16(r.x, r.y, hi, lo);
                    size_t moff = ((size_t)row * Bb + b) * Ff + col;
                    *(uint32_t*)&g_hH[moff] = hi;
                    *(uint32_t*)&g_hL[moff] = lo;
                }
            }
        }
    }
}

extern "C" void kernel_launch(void* const* d_in, const int* in_sizes, int n_in,
                              void* d_out, int out_size) {
    const float* x   = (const float*)d_in[0];
    const float* adj = (const float*)d_in[1];
    const float* W1  = (const float*)d_in[2];
    const float* b1  = (const float*)d_in[3];
    const float* Wh1 = (const float*)d_in[4];
    const float* bh1 = (const float*)d_in[5];
    const float* W2  = (const float*)d_in[6];
    const float* b2  = (const float*)d_in[7];
    const float* Wh2 = (const float*)d_in[8];
    const float* bh2 = (const float*)d_in[9];
    float* out = (float*)d_out;

    static int attr_done = 0;
    if (!attr_done) {
        cudaFuncSetAttribute(gemm1_mma, cudaFuncAttributeMaxDynamicSharedMemorySize, SMEM1_TOTAL);
        cudaFuncSetAttribute(gemm2_mma, cudaFuncAttributeMaxDynamicSharedMemorySize, SMEM2_TOTAL);
        attr_done = 1;
    }

    dim3 g1(Mrows / 128, 4);   // (256, 4)
    dim3 g2(Nn / 128, Bb);     // (4, 64)

    // Layer 1
    prep_weights<<<Ff * Jcols / 2 / 256, 256>>>(W1, b1, Wh1, bh1);
    x_split<<<Mrows * Ff / 4 / 256, 256>>>(x);
    gemm1_mma<<<g1, 256, SMEM1_TOTAL>>>(0);
    gemm2_mma<<<g2, 256, SMEM2_TOTAL>>>(adj, x, 0, nullptr, 1);   // -> g_h (+planes)
    // Layer 2
    prep_weights<<<Ff * Jcols / 2 / 256, 256>>>(W2, b2, Wh2, bh2);
    gemm1_mma<<<g1, 256, SMEM1_TOTAL>>>(1);
    gemm2_mma<<<g2, 256, SMEM2_TOTAL>>>(adj, nullptr, 1, out, 0); // -> d_out
}

// round 8
// speedup vs baseline: 3.5897x; 1.1748x over previous
#include <cuda_runtime.h>
#include <cuda_fp16.h>
#include <math.h>
#include <stdint.h>

// Problem constants
#define Nn 512
#define Bb 64
#define Ff 128
#define Oo 128
#define Ee 3
#define Mrows (Nn*Bb)     // 32768
#define Jcols 512         // 3*O + O(highway)

// Scratch (static device globals)
__device__ float g_t[(size_t)Mrows*Oo];          // sigmoid gate [m, o]
__device__ float g_h[(size_t)Mrows*Oo];          // layer-1 output fp32 (highway X)
__device__ float g_bcat[Jcols];
__device__ __half g_WcatH[Ff*Jcols];             // weights fp16 (single plane)
__device__ __half g_xH[(size_t)Mrows*Ff];        // layer-1 X planes (hi/lo)
__device__ __half g_xL[(size_t)Mrows*Ff];
__device__ __half g_hH[(size_t)Mrows*Ff];        // layer-2 X planes
__device__ __half g_hL[(size_t)Mrows*Ff];
// support fp16 (single plane) [e,b,n,o]
__device__ __half g_supH[(size_t)Ee*Bb*Nn*Oo];

// ---- fp16 split / convert ----
__device__ __forceinline__ void cvt_split16(float x, float y, uint32_t& hi, uint32_t& lo) {
    __half2 h = __floats2half2_rn(x, y);
    float2 hf = __half22float2(h);
    __half2 l = __floats2half2_rn(x - hf.x, y - hf.y);
    hi = *reinterpret_cast<uint32_t*>(&h);
    lo = *reinterpret_cast<uint32_t*>(&l);
}
__device__ __forceinline__ uint32_t cvt16(float x, float y) {
    __half2 h = __floats2half2_rn(x, y);
    return *reinterpret_cast<uint32_t*>(&h);
}

__device__ __forceinline__ uint32_t smem_u32(const void* p) {
    uint32_t a;
    asm("{ .reg .u64 t; cvta.to.shared.u64 t, %1; cvt.u32.u64 %0, t; }" : "=r"(a) : "l"(p));
    return a;
}

// ---- cp.async ----
__device__ __forceinline__ void cpa16(uint32_t saddr, const void* g) {
    asm volatile("cp.async.cg.shared.global [%0], [%1], 16;" :: "r"(saddr), "l"(g));
}
__device__ __forceinline__ void cpa_commit() {
    asm volatile("cp.async.commit_group;" ::: "memory");
}
__device__ __forceinline__ void cpa_wait0() {
    asm volatile("cp.async.wait_group 0;" ::: "memory");
}

// ---- warp-level MMA primitives (fp16 in, fp32 accum) ----
__device__ __forceinline__ void ldsm4(uint32_t r[4], uint32_t addr) {
    asm volatile("ldmatrix.sync.aligned.m8n8.x4.shared.b16 {%0,%1,%2,%3}, [%4];"
                 : "=r"(r[0]), "=r"(r[1]), "=r"(r[2]), "=r"(r[3]) : "r"(addr));
}
__device__ __forceinline__ void ldsm4t(uint32_t r[4], uint32_t addr) {
    asm volatile("ldmatrix.sync.aligned.m8n8.x4.trans.shared.b16 {%0,%1,%2,%3}, [%4];"
                 : "=r"(r[0]), "=r"(r[1]), "=r"(r[2]), "=r"(r[3]) : "r"(addr));
}
__device__ __forceinline__ void mma16816(float c[4], const uint32_t a[4], const uint32_t b[2]) {
    asm volatile(
        "mma.sync.aligned.m16n8k16.row.col.f32.f16.f16.f32 "
        "{%0,%1,%2,%3}, {%4,%5,%6,%7}, {%8,%9}, {%0,%1,%2,%3};"
        : "+f"(c[0]), "+f"(c[1]), "+f"(c[2]), "+f"(c[3])
        : "r"(a[0]), "r"(a[1]), "r"(a[2]), "r"(a[3]), "r"(b[0]), "r"(b[1]));
}

// ---- shared tile geometry ----
#define ASTR 40       // A smem row stride (half elems), 80 B
#define BSTR 136      // B smem row stride (half elems), 272 B
#define A_PLANE 10240 // 128*40*2 bytes
#define B_PLANE 8704  // 32*136*2 bytes
#define AH_OFF 0
#define AL_OFF A_PLANE
// gemm1: A hi/lo + B hi         BH at 2*A_PLANE
#define BH1_OFF (2*A_PLANE)
#define BUFSTRIDE1 (2*A_PLANE + B_PLANE)    // 29184
#define SMEM1_TOTAL (2*BUFSTRIDE1)          // 58368
// gemm2: A hi + B hi            BH at A_PLANE
#define BH2_OFF A_PLANE
#define BUFSTRIDE2 (A_PLANE + B_PLANE)      // 18944
#define SMEM2_TOTAL (2*BUFSTRIDE2)          // 37888

// 2-pass compute (gemm1): (Xh + Xl) * Wh
__device__ __forceinline__ void mma_compute_g1(uint32_t sb, int lane, int wm, int wn,
                                               float acc[4][4][4]) {
    #pragma unroll
    for (int ks = 0; ks < 2; ++ks) {
        int k0 = ks * 16;
        uint32_t abase = sb + ((wm * 64 + (lane & 15)) * ASTR + k0 + ((lane >> 4) << 3)) * 2;
        uint32_t bbase = sb + ((k0 + (lane & 15)) * BSTR + wn * 32 + ((lane >> 4) << 3)) * 2;

        uint32_t ah[4][4], bhf[4][2];
        #pragma unroll
        for (int mi = 0; mi < 4; ++mi)
            ldsm4(ah[mi], abase + AH_OFF + mi * 16 * ASTR * 2);
        #pragma unroll
        for (int g = 0; g < 2; ++g) {
            uint32_t r[4];
            ldsm4t(r, bbase + BH1_OFF + g * 32);
            bhf[g*2][0] = r[0]; bhf[g*2][1] = r[1];
            bhf[g*2+1][0] = r[2]; bhf[g*2+1][1] = r[3];
        }
        #pragma unroll
        for (int mi = 0; mi < 4; ++mi)
            #pragma unroll
            for (int ni = 0; ni < 4; ++ni)
                mma16816(acc[mi][ni], ah[mi], bhf[ni]);   // H*W
        uint32_t al[4][4];
        #pragma unroll
        for (int mi = 0; mi < 4; ++mi)
            ldsm4(al[mi], abase + AL_OFF + mi * 16 * ASTR * 2);
        #pragma unroll
        for (int mi = 0; mi < 4; ++mi)
            #pragma unroll
            for (int ni = 0; ni < 4; ++ni)
                mma16816(acc[mi][ni], al[mi], bhf[ni]);   // L*W
    }
}

// 1-pass compute (gemm2): Ah * Bh
__device__ __forceinline__ void mma_compute_g2(uint32_t sb, int lane, int wm, int wn,
                                               float acc[4][4][4]) {
    #pragma unroll
    for (int ks = 0; ks < 2; ++ks) {
        int k0 = ks * 16;
        uint32_t abase = sb + ((wm * 64 + (lane & 15)) * ASTR + k0 + ((lane >> 4) << 3)) * 2;
        uint32_t bbase = sb + ((k0 + (lane & 15)) * BSTR + wn * 32 + ((lane >> 4) << 3)) * 2;

        uint32_t ah[4][4], bhf[4][2];
        #pragma unroll
        for (int mi = 0; mi < 4; ++mi)
            ldsm4(ah[mi], abase + AH_OFF + mi * 16 * ASTR * 2);
        #pragma unroll
        for (int g = 0; g < 2; ++g) {
            uint32_t r[4];
            ldsm4t(r, bbase + BH2_OFF + g * 32);
            bhf[g*2][0] = r[0]; bhf[g*2][1] = r[1];
            bhf[g*2+1][0] = r[2]; bhf[g*2+1][1] = r[3];
        }
        #pragma unroll
        for (int mi = 0; mi < 4; ++mi)
            #pragma unroll
            for (int ni = 0; ni < 4; ++ni)
                mma16816(acc[mi][ni], ah[mi], bhf[ni]);
    }
}

// ---------------------------------------------------------------------------
// prep_weights: W/Wh -> fp16 plane [f][j], biases fp32
// ---------------------------------------------------------------------------
__global__ void prep_weights(const float* __restrict__ W, const float* __restrict__ b,
                             const float* __restrict__ Wh, const float* __restrict__ bh) {
    int idx = blockIdx.x * blockDim.x + threadIdx.x;   // over Ff*Jcols/2 pairs
    if (idx < Ff * Jcols / 2) {
        int f = idx / (Jcols / 2), jp = idx % (Jcols / 2);
        int j = jp * 2;
        float v0, v1;
        if (j < 3 * Oo) {
            int e = j >> 7, o = j & 127;
            v0 = W[((size_t)e * Ff + f) * Oo + o];
            v1 = W[((size_t)e * Ff + f) * Oo + o + 1];
        } else {
            v0 = Wh[(size_t)f * Oo + (j - 3 * Oo)];
            v1 = Wh[(size_t)f * Oo + (j - 3 * Oo) + 1];
        }
        *(uint32_t*)&g_WcatH[f * Jcols + j] = cvt16(v0, v1);
    }
    if (idx < Jcols) {
        int j = idx;
        g_bcat[j] = (j < 3 * Oo) ? b[(j >> 7) * Oo + (j & 127)] : bh[j - 3 * Oo];
    }
}

// ---------------------------------------------------------------------------
// x_split: fp32 [m,f] -> fp16 hi/lo planes (layer-1 X)
// ---------------------------------------------------------------------------
__global__ void x_split(const float* __restrict__ x) {
    int i = blockIdx.x * blockDim.x + threadIdx.x;   // over float4 slots
    float4 v = ((const float4*)x)[i];
    uint32_t h01, l01, h23, l23;
    cvt_split16(v.x, v.y, h01, l01);
    cvt_split16(v.z, v.w, h23, l23);
    ((uint2*)g_xH)[i] = make_uint2(h01, h23);
    ((uint2*)g_xL)[i] = make_uint2(l01, l23);
}

// ---------------------------------------------------------------------------
// GEMM1 on mma.sync (fp16 2-pass): C[m, j] = X[m,:] @ Wcat[:, jb*128..] + bias
// grid (Mrows/128, 4). NCH=4.
// ---------------------------------------------------------------------------
__global__ __launch_bounds__(256, 2) void gemm1_mma(int x_from_h) {
    extern __shared__ char smem[];
    const __half* __restrict__ XH = x_from_h ? g_hH : g_xH;
    const __half* __restrict__ XL = x_from_h ? g_hL : g_xL;
    uint32_t sbase = smem_u32(smem);

    int tid = threadIdx.x, lane = tid & 31, wid = tid >> 5;
    int wm = wid & 1, wn = wid >> 1;
    int m0 = blockIdx.x * 128, jb = blockIdx.y;

    float acc[4][4][4];
    #pragma unroll
    for (int mi = 0; mi < 4; ++mi)
        #pragma unroll
        for (int ni = 0; ni < 4; ++ni)
            #pragma unroll
            for (int r = 0; r < 4; ++r) acc[mi][ni][r] = 0.f;

    auto issue = [&](int c) {
        uint32_t sb = sbase + (c & 1) * BUFSTRIDE1;
        int k0 = c * 32;
        #pragma unroll
        for (int q = 0; q < 2; ++q) {           // A: 128 rows x 32 k, hi+lo
            int i = q * 256 + tid;
            int row = i >> 2, c8 = i & 3;
            uint32_t so = row * (ASTR * 2) + c8 * 16;
            size_t go = (size_t)(m0 + row) * Ff + k0 + c8 * 8;
            cpa16(sb + AH_OFF + so, XH + go);
            cpa16(sb + AL_OFF + so, XL + go);
        }
        #pragma unroll
        for (int q = 0; q < 2; ++q) {           // B: 32 rows x 128 cols, hi only
            int i = q * 256 + tid;
            int row = i >> 4, c8 = i & 15;
            uint32_t so = row * (BSTR * 2) + c8 * 16;
            cpa16(sb + BH1_OFF + so, g_WcatH + (size_t)(k0 + row) * Jcols + jb * 128 + c8 * 8);
        }
        cpa_commit();
    };

    issue(0);
    #pragma unroll
    for (int c = 0; c < 4; ++c) {
        cpa_wait0();
        __syncthreads();
        if (c + 1 < 4) issue(c + 1);
        mma_compute_g1(sbase + (c & 1) * BUFSTRIDE1, lane, wm, wn, acc);
        if (c + 1 < 4) __syncthreads();
    }

    // epilogue: add bias; jb<3 -> fp16 support; jb==3 -> sigmoid -> g_t
    #pragma unroll
    for (int mi = 0; mi < 4; ++mi) {
        #pragma unroll
        for (int ni = 0; ni < 4; ++ni) {
            int col = wn * 32 + ni * 8 + (lane & 3) * 2;
            float bb0 = g_bcat[jb * 128 + col], bb1 = g_bcat[jb * 128 + col + 1];
            #pragma unroll
            for (int h = 0; h < 2; ++h) {
                int m = m0 + wm * 64 + mi * 16 + (lane >> 2) + h * 8;
                float d0 = acc[mi][ni][h * 2 + 0] + bb0;
                float d1 = acc[mi][ni][h * 2 + 1] + bb1;
                if (jb < 3) {
                    int n = m >> 6, bidx = m & 63;
                    size_t off = (((size_t)jb * Bb + bidx) * Nn + n) * Oo + col;
                    *(uint32_t*)&g_supH[off] = cvt16(d0, d1);
                } else {
                    float2 r;
                    r.x = 1.f / (1.f + expf(-d0));
                    r.y = 1.f / (1.f + expf(-d1));
                    *(float2*)&g_t[(size_t)m * Oo + col] = r;
                }
            }
        }
    }
}

// ---------------------------------------------------------------------------
// GEMM2 on mma.sync (fp16 1-pass): out[m,b,:] = relu(sum adj*sup) gated
// grid (4, 64). B (supH) via cp.async; A (adj fp32) register-staged + cvt hi.
// ---------------------------------------------------------------------------
#define NCH2 48

__global__ __launch_bounds__(256, 2) void gemm2_mma(const float* __restrict__ adj,
                                                    const float* __restrict__ Xin, int x_from_h,
                                                    float* __restrict__ OutExt, int out_to_h) {
    extern __shared__ char smem[];
    const float* __restrict__ X = x_from_h ? g_h : Xin;
    float* __restrict__ Out = out_to_h ? g_h : OutExt;
    uint32_t sbase = smem_u32(smem);

    int tid = threadIdx.x, lane = tid & 31, wid = tid >> 5;
    int wm = wid & 1, wn = wid >> 1;
    int m0 = blockIdx.x * 128, b = blockIdx.y;

    float acc[4][4][4];
    #pragma unroll
    for (int mi = 0; mi < 4; ++mi)
        #pragma unroll
        for (int ni = 0; ni < 4; ++ni)
            #pragma unroll
            for (int r = 0; r < 4; ++r) acc[mi][ni][r] = 0.f;

    int arow[4], ac4[4];
    #pragma unroll
    for (int q = 0; q < 4; ++q) { int i = q * 256 + tid; arow[q] = i >> 3; ac4[q] = i & 7; }
    float4 av[4];

    auto issueB = [&](int c) {
        uint32_t sb = sbase + (c & 1) * BUFSTRIDE2;
        int e = c >> 4, n0 = (c & 15) * 32;
        size_t gb = (((size_t)e * Bb + b) * Nn + n0) * Oo;
        #pragma unroll
        for (int q = 0; q < 2; ++q) {
            int i = q * 256 + tid;
            int row = i >> 4, c8 = i & 15;
            uint32_t so = row * (BSTR * 2) + c8 * 16;
            cpa16(sb + BH2_OFF + so, g_supH + gb + (size_t)row * Oo + c8 * 8);
        }
        cpa_commit();
    };
    auto loadA = [&](int c) {
        int e = c >> 4, n0 = (c & 15) * 32;
        const float* ab = adj + (((size_t)e * Bb + b) * Nn + m0) * Nn + n0;
        #pragma unroll
        for (int q = 0; q < 4; ++q)
            av[q] = *(const float4*)(ab + (size_t)arow[q] * Nn + ac4[q] * 4);
    };
    auto storeA = [&](int c) {
        uint32_t off = (c & 1) * BUFSTRIDE2;
        #pragma unroll
        for (int q = 0; q < 4; ++q) {
            uint32_t h01 = cvt16(av[q].x, av[q].y);
            uint32_t h23 = cvt16(av[q].z, av[q].w);
            uint32_t so = arow[q] * (ASTR * 2) + ac4[q] * 8;
            *(uint2*)(smem + off + AH_OFF + so) = make_uint2(h01, h23);
        }
    };

    issueB(0);
    loadA(0);
    storeA(0);
    for (int c = 0; c < NCH2; ++c) {
        cpa_wait0();
        __syncthreads();
        if (c + 1 < NCH2) { issueB(c + 1); loadA(c + 1); }
        mma_compute_g2(sbase + (c & 1) * BUFSTRIDE2, lane, wm, wn, acc);
        if (c + 1 < NCH2) storeA(c + 1);
    }

    // epilogue: relu + highway gate (+ fp16 plane emit for layer-1 output)
    #pragma unroll
    for (int mi = 0; mi < 4; ++mi) {
        #pragma unroll
        for (int ni = 0; ni < 4; ++ni) {
            int col = wn * 32 + ni * 8 + (lane & 3) * 2;
            #pragma unroll
            for (int h = 0; h < 2; ++h) {
                int row = m0 + wm * 64 + mi * 16 + (lane >> 2) + h * 8;
                float d0 = acc[mi][ni][h * 2 + 0];
                float d1 = acc[mi][ni][h * 2 + 1];
                size_t base = ((size_t)row * Bb + b) * Oo + col;
                float2 tv = *(const float2*)&g_t[base];
                float2 xv = *(const float2*)&X[base];
                float2 r;
                r.x = fmaxf(d0, 0.f) * tv.x + xv.x * (1.f - tv.x);
                r.y = fmaxf(d1, 0.f) * tv.y + xv.y * (1.f - tv.y);
                *(float2*)&Out[base] = r;
                if (out_to_h) {
                    uint32_t hi, lo;
                    cvt_split16(r.x, r.y, hi, lo);
                    size_t moff = ((size_t)row * Bb + b) * Ff + col;
                    *(uint32_t*)&g_hH[moff] = hi;
                    *(uint32_t*)&g_hL[moff] = lo;
                }
            }
        }
    }
}

extern "C" void kernel_launch(void* const* d_in, const int* in_sizes, int n_in,
                              void* d_out, int out_size) {
    const float* x   = (const float*)d_in[0];
    const float* adj = (const float*)d_in[1];
    const float* W1  = (const float*)d_in[2];
    const float* b1  = (const float*)d_in[3];
    const float* Wh1 = (const float*)d_in[4];
    const float* bh1 = (const float*)d_in[5];
    const float* W2  = (const float*)d_in[6];
    const float* b2  = (const float*)d_in[7];
    const float* Wh2 = (const float*)d_in[8];
    const float* bh2 = (const float*)d_in[9];
    float* out = (float*)d_out;

    static int attr_done = 0;
    if (!attr_done) {
        cudaFuncSetAttribute(gemm1_mma, cudaFuncAttributeMaxDynamicSharedMemorySize, SMEM1_TOTAL);
        cudaFuncSetAttribute(gemm2_mma, cudaFuncAttributeMaxDynamicSharedMemorySize, SMEM2_TOTAL);
        attr_done = 1;
    }

    dim3 g1(Mrows / 128, 4);   // (256, 4)
    dim3 g2(Nn / 128, Bb);     // (4, 64)

    // Layer 1
    prep_weights<<<Ff * Jcols / 2 / 256, 256>>>(W1, b1, Wh1, bh1);
    x_split<<<Mrows * Ff / 4 / 256, 256>>>(x);
    gemm1_mma<<<g1, 256, SMEM1_TOTAL>>>(0);
    gemm2_mma<<<g2, 256, SMEM2_TOTAL>>>(adj, x, 0, nullptr, 1);   // -> g_h (+planes)
    // Layer 2
    prep_weights<<<Ff * Jcols / 2 / 256, 256>>>(W2, b2, Wh2, bh2);
    gemm1_mma<<<g1, 256, SMEM1_TOTAL>>>(1);
    gemm2_mma<<<g2, 256, SMEM2_TOTAL>>>(adj, nullptr, 1, out, 0); // -> d_out
}

// round 9
// speedup vs baseline: 3.9476x; 1.0997x over previous
#include <cuda_runtime.h>
#include <cuda_fp16.h>
#include <math.h>
#include <stdint.h>

// Problem constants
#define Nn 512
#define Bb 64
#define Ff 128
#define Oo 128
#define Ee 3
#define Mrows (Nn*Bb)     // 32768
#define Jcols 512         // 3*O + O(highway)

// Scratch (static device globals)
__device__ float g_t[(size_t)Mrows*Oo];          // sigmoid gate [m, o]
__device__ float g_h[(size_t)Mrows*Oo];          // layer-1 output fp32 (highway X)
__device__ float g_bcat[Jcols];
__device__ __half g_WcatH[Ff*Jcols];             // weights fp16
__device__ __half g_xH[(size_t)Mrows*Ff];        // layer-1 X fp16
__device__ __half g_hH[(size_t)Mrows*Ff];        // layer-2 X fp16
__device__ __half g_supH[(size_t)Ee*Bb*Nn*Oo];   // support fp16 [e,b,n,o]
__device__ __half g_adjH[(size_t)Ee*Bb*Nn*Nn];   // adj fp16 (emitted by layer-1 gemm2)

// ---- fp16 convert ----
__device__ __forceinline__ uint32_t cvt16(float x, float y) {
    __half2 h = __floats2half2_rn(x, y);
    return *reinterpret_cast<uint32_t*>(&h);
}

__device__ __forceinline__ uint32_t smem_u32(const void* p) {
    uint32_t a;
    asm("{ .reg .u64 t; cvta.to.shared.u64 t, %1; cvt.u32.u64 %0, t; }" : "=r"(a) : "l"(p));
    return a;
}

// ---- cp.async ----
__device__ __forceinline__ void cpa16(uint32_t saddr, const void* g) {
    asm volatile("cp.async.cg.shared.global [%0], [%1], 16;" :: "r"(saddr), "l"(g));
}
__device__ __forceinline__ void cpa_commit() {
    asm volatile("cp.async.commit_group;" ::: "memory");
}
__device__ __forceinline__ void cpa_wait0() {
    asm volatile("cp.async.wait_group 0;" ::: "memory");
}
__device__ __forceinline__ void cpa_wait1() {
    asm volatile("cp.async.wait_group 1;" ::: "memory");
}

// ---- warp-level MMA primitives (fp16 in, fp32 accum) ----
__device__ __forceinline__ void ldsm4(uint32_t r[4], uint32_t addr) {
    asm volatile("ldmatrix.sync.aligned.m8n8.x4.shared.b16 {%0,%1,%2,%3}, [%4];"
                 : "=r"(r[0]), "=r"(r[1]), "=r"(r[2]), "=r"(r[3]) : "r"(addr));
}
__device__ __forceinline__ void ldsm4t(uint32_t r[4], uint32_t addr) {
    asm volatile("ldmatrix.sync.aligned.m8n8.x4.trans.shared.b16 {%0,%1,%2,%3}, [%4];"
                 : "=r"(r[0]), "=r"(r[1]), "=r"(r[2]), "=r"(r[3]) : "r"(addr));
}
__device__ __forceinline__ void mma16816(float c[4], const uint32_t a[4], const uint32_t b[2]) {
    asm volatile(
        "mma.sync.aligned.m16n8k16.row.col.f32.f16.f16.f32 "
        "{%0,%1,%2,%3}, {%4,%5,%6,%7}, {%8,%9}, {%0,%1,%2,%3};"
        : "+f"(c[0]), "+f"(c[1]), "+f"(c[2]), "+f"(c[3])
        : "r"(a[0]), "r"(a[1]), "r"(a[2]), "r"(a[3]), "r"(b[0]), "r"(b[1]));
}

// ---- shared tile geometry (unified for all GEMMs) ----
#define ASTR 40       // A smem row stride (half elems), 80 B
#define BSTR 136      // B smem row stride (half elems), 272 B
#define A_PLANE 10240 // 128*40*2 bytes
#define B_PLANE 8704  // 32*136*2 bytes
#define BH_OFF A_PLANE
#define BUFSTRIDE (A_PLANE + B_PLANE)   // 18944
#define SMEM_2B (2*BUFSTRIDE)           // 37888 (gemm1, gemm2 L1)
#define SMEM_3B (3*BUFSTRIDE)           // 56832 (gemm2 L2, 3-stage)

// 1-pass compute: Ah * Bh on one staged buffer. 2x4 warp grid, 64x32 warp tiles.
__device__ __forceinline__ void mma_compute1(uint32_t sb, int lane, int wm, int wn,
                                             float acc[4][4][4]) {
    #pragma unroll
    for (int ks = 0; ks < 2; ++ks) {
        int k0 = ks * 16;
        uint32_t abase = sb + ((wm * 64 + (lane & 15)) * ASTR + k0 + ((lane >> 4) << 3)) * 2;
        uint32_t bbase = sb + ((k0 + (lane & 15)) * BSTR + wn * 32 + ((lane >> 4) << 3)) * 2;

        uint32_t ah[4][4], bhf[4][2];
        #pragma unroll
        for (int mi = 0; mi < 4; ++mi)
            ldsm4(ah[mi], abase + mi * 16 * ASTR * 2);
        #pragma unroll
        for (int g = 0; g < 2; ++g) {
            uint32_t r[4];
            ldsm4t(r, bbase + BH_OFF + g * 32);
            bhf[g*2][0] = r[0]; bhf[g*2][1] = r[1];
            bhf[g*2+1][0] = r[2]; bhf[g*2+1][1] = r[3];
        }
        #pragma unroll
        for (int mi = 0; mi < 4; ++mi)
            #pragma unroll
            for (int ni = 0; ni < 4; ++ni)
                mma16816(acc[mi][ni], ah[mi], bhf[ni]);
    }
}

// ---------------------------------------------------------------------------
// prep_weights: W/Wh -> fp16 plane [f][j], biases fp32
// ---------------------------------------------------------------------------
__global__ void prep_weights(const float* __restrict__ W, const float* __restrict__ b,
                             const float* __restrict__ Wh, const float* __restrict__ bh) {
    int idx = blockIdx.x * blockDim.x + threadIdx.x;
    if (idx < Ff * Jcols / 2) {
        int f = idx / (Jcols / 2), jp = idx % (Jcols / 2);
        int j = jp * 2;
        float v0, v1;
        if (j < 3 * Oo) {
            int e = j >> 7, o = j & 127;
            v0 = W[((size_t)e * Ff + f) * Oo + o];
            v1 = W[((size_t)e * Ff + f) * Oo + o + 1];
        } else {
            v0 = Wh[(size_t)f * Oo + (j - 3 * Oo)];
            v1 = Wh[(size_t)f * Oo + (j - 3 * Oo) + 1];
        }
        *(uint32_t*)&g_WcatH[f * Jcols + j] = cvt16(v0, v1);
    }
    if (idx < Jcols) {
        int j = idx;
        g_bcat[j] = (j < 3 * Oo) ? b[(j >> 7) * Oo + (j & 127)] : bh[j - 3 * Oo];
    }
}

// ---------------------------------------------------------------------------
// x_split: fp32 [m,f] -> fp16 plane (layer-1 X)
// ---------------------------------------------------------------------------
__global__ void x_split(const float* __restrict__ x) {
    int i = blockIdx.x * blockDim.x + threadIdx.x;   // over float4 slots
    float4 v = ((const float4*)x)[i];
    ((uint2*)g_xH)[i] = make_uint2(cvt16(v.x, v.y), cvt16(v.z, v.w));
}

// ---------------------------------------------------------------------------
// GEMM1 (fp16 1-pass): C[m, j] = X[m,:] @ Wcat[:, jb*128..] + bias
// grid (Mrows/128, 4). NCH=4, double-buffered.
// ---------------------------------------------------------------------------
__global__ __launch_bounds__(256, 2) void gemm1_mma(int x_from_h) {
    extern __shared__ char smem[];
    const __half* __restrict__ XH = x_from_h ? g_hH : g_xH;
    uint32_t sbase = smem_u32(smem);

    int tid = threadIdx.x, lane = tid & 31, wid = tid >> 5;
    int wm = wid & 1, wn = wid >> 1;
    int m0 = blockIdx.x * 128, jb = blockIdx.y;

    float acc[4][4][4];
    #pragma unroll
    for (int mi = 0; mi < 4; ++mi)
        #pragma unroll
        for (int ni = 0; ni < 4; ++ni)
            #pragma unroll
            for (int r = 0; r < 4; ++r) acc[mi][ni][r] = 0.f;

    auto issue = [&](int c) {
        uint32_t sb = sbase + (c & 1) * BUFSTRIDE;
        int k0 = c * 32;
        #pragma unroll
        for (int q = 0; q < 2; ++q) {           // A: 128 rows x 32 k
            int i = q * 256 + tid;
            int row = i >> 2, c4 = i & 3;
            cpa16(sb + row * (ASTR * 2) + c4 * 16,
                  XH + (size_t)(m0 + row) * Ff + k0 + c4 * 8);
        }
        #pragma unroll
        for (int q = 0; q < 2; ++q) {           // B: 32 rows x 128 cols
            int i = q * 256 + tid;
            int row = i >> 4, c8 = i & 15;
            cpa16(sb + BH_OFF + row * (BSTR * 2) + c8 * 16,
                  g_WcatH + (size_t)(k0 + row) * Jcols + jb * 128 + c8 * 8);
        }
        cpa_commit();
    };

    issue(0);
    #pragma unroll
    for (int c = 0; c < 4; ++c) {
        cpa_wait0();
        __syncthreads();
        if (c + 1 < 4) issue(c + 1);
        mma_compute1(sbase + (c & 1) * BUFSTRIDE, lane, wm, wn, acc);
        if (c + 1 < 4) __syncthreads();
    }

    // epilogue
    #pragma unroll
    for (int mi = 0; mi < 4; ++mi) {
        #pragma unroll
        for (int ni = 0; ni < 4; ++ni) {
            int col = wn * 32 + ni * 8 + (lane & 3) * 2;
            float bb0 = g_bcat[jb * 128 + col], bb1 = g_bcat[jb * 128 + col + 1];
            #pragma unroll
            for (int h = 0; h < 2; ++h) {
                int m = m0 + wm * 64 + mi * 16 + (lane >> 2) + h * 8;
                float d0 = acc[mi][ni][h * 2 + 0] + bb0;
                float d1 = acc[mi][ni][h * 2 + 1] + bb1;
                if (jb < 3) {
                    int n = m >> 6, bidx = m & 63;
                    size_t off = (((size_t)jb * Bb + bidx) * Nn + n) * Oo + col;
                    *(uint32_t*)&g_supH[off] = cvt16(d0, d1);
                } else {
                    float2 r;
                    r.x = 1.f / (1.f + expf(-d0));
                    r.y = 1.f / (1.f + expf(-d1));
                    *(float2*)&g_t[(size_t)m * Oo + col] = r;
                }
            }
        }
    }
}

// ---------------------------------------------------------------------------
// GEMM2 layer 1 (fp32 adj, register cvt, EMITS g_adjH): out -> g_h (+g_hH)
// grid (4, 64). NCH=48, double-buffered.
// ---------------------------------------------------------------------------
#define NCH2 48

__global__ __launch_bounds__(256, 2) void gemm2_mma(const float* __restrict__ adj,
                                                    const float* __restrict__ Xin) {
    extern __shared__ char smem[];
    uint32_t sbase = smem_u32(smem);

    int tid = threadIdx.x, lane = tid & 31, wid = tid >> 5;
    int wm = wid & 1, wn = wid >> 1;
    int m0 = blockIdx.x * 128, b = blockIdx.y;

    float acc[4][4][4];
    #pragma unroll
    for (int mi = 0; mi < 4; ++mi)
        #pragma unroll
        for (int ni = 0; ni < 4; ++ni)
            #pragma unroll
            for (int r = 0; r < 4; ++r) acc[mi][ni][r] = 0.f;

    int arow[4], ac4[4];
    #pragma unroll
    for (int q = 0; q < 4; ++q) { int i = q * 256 + tid; arow[q] = i >> 3; ac4[q] = i & 7; }
    float4 av[4];

    auto issueB = [&](int c) {
        uint32_t sb = sbase + (c & 1) * BUFSTRIDE;
        int e = c >> 4, n0 = (c & 15) * 32;
        size_t gb = (((size_t)e * Bb + b) * Nn + n0) * Oo;
        #pragma unroll
        for (int q = 0; q < 2; ++q) {
            int i = q * 256 + tid;
            int row = i >> 4, c8 = i & 15;
            cpa16(sb + BH_OFF + row * (BSTR * 2) + c8 * 16,
                  g_supH + gb + (size_t)row * Oo + c8 * 8);
        }
        cpa_commit();
    };
    auto loadA = [&](int c) {
        int e = c >> 4, n0 = (c & 15) * 32;
        const float* ab = adj + (((size_t)e * Bb + b) * Nn + m0) * Nn + n0;
        #pragma unroll
        for (int q = 0; q < 4; ++q)
            av[q] = *(const float4*)(ab + (size_t)arow[q] * Nn + ac4[q] * 4);
    };
    auto storeA = [&](int c) {
        uint32_t off = (c & 1) * BUFSTRIDE;
        int e = c >> 4, n0 = (c & 15) * 32;
        size_t ah_base = (((size_t)e * Bb + b) * Nn + m0) * Nn + n0;
        #pragma unroll
        for (int q = 0; q < 4; ++q) {
            uint32_t h01 = cvt16(av[q].x, av[q].y);
            uint32_t h23 = cvt16(av[q].z, av[q].w);
            *(uint2*)(smem + off + arow[q] * (ASTR * 2) + ac4[q] * 8) = make_uint2(h01, h23);
            // emit fp16 adj for layer 2
            *(uint2*)&g_adjH[ah_base + (size_t)arow[q] * Nn + ac4[q] * 4] = make_uint2(h01, h23);
        }
    };

    issueB(0);
    loadA(0);
    storeA(0);
    for (int c = 0; c < NCH2; ++c) {
        cpa_wait0();
        __syncthreads();
        if (c + 1 < NCH2) { issueB(c + 1); loadA(c + 1); }
        mma_compute1(sbase + (c & 1) * BUFSTRIDE, lane, wm, wn, acc);
        if (c + 1 < NCH2) storeA(c + 1);
    }

    // epilogue: relu + highway gate -> g_h fp32 + g_hH fp16
    #pragma unroll
    for (int mi = 0; mi < 4; ++mi) {
        #pragma unroll
        for (int ni = 0; ni < 4; ++ni) {
            int col = wn * 32 + ni * 8 + (lane & 3) * 2;
            #pragma unroll
            for (int h = 0; h < 2; ++h) {
                int row = m0 + wm * 64 + mi * 16 + (lane >> 2) + h * 8;
                float d0 = acc[mi][ni][h * 2 + 0];
                float d1 = acc[mi][ni][h * 2 + 1];
                size_t base = ((size_t)row * Bb + b) * Oo + col;
                float2 tv = *(const float2*)&g_t[base];
                float2 xv = *(const float2*)&Xin[base];
                float2 r;
                r.x = fmaxf(d0, 0.f) * tv.x + xv.x * (1.f - tv.x);
                r.y = fmaxf(d1, 0.f) * tv.y + xv.y * (1.f - tv.y);
                *(float2*)&g_h[base] = r;
                *(uint32_t*)&g_hH[base] = cvt16(r.x, r.y);
            }
        }
    }
}

// ---------------------------------------------------------------------------
// GEMM2 layer 2 (pure fp16, 3-stage cp.async): out -> d_out
// grid (4, 64). A from g_adjH, B from g_supH.
// ---------------------------------------------------------------------------
__global__ __launch_bounds__(256, 2) void gemm2_f16(float* __restrict__ Out) {
    extern __shared__ char smem[];
    uint32_t sbase = smem_u32(smem);

    int tid = threadIdx.x, lane = tid & 31, wid = tid >> 5;
    int wm = wid & 1, wn = wid >> 1;
    int m0 = blockIdx.x * 128, b = blockIdx.y;

    float acc[4][4][4];
    #pragma unroll
    for (int mi = 0; mi < 4; ++mi)
        #pragma unroll
        for (int ni = 0; ni < 4; ++ni)
            #pragma unroll
            for (int r = 0; r < 4; ++r) acc[mi][ni][r] = 0.f;

    auto issue = [&](int c) {
        uint32_t sb = sbase + (c % 3) * BUFSTRIDE;
        int e = c >> 4, n0 = (c & 15) * 32;
        size_t ab = (((size_t)e * Bb + b) * Nn + m0) * Nn + n0;
        #pragma unroll
        for (int q = 0; q < 2; ++q) {           // A: 128 rows x 32 halfs (4x16B per row)
            int i = q * 256 + tid;
            int row = i >> 2, c4 = i & 3;
            cpa16(sb + row * (ASTR * 2) + c4 * 16,
                  g_adjH + ab + (size_t)row * Nn + c4 * 8);
        }
        size_t gb = (((size_t)e * Bb + b) * Nn + n0) * Oo;
        #pragma unroll
        for (int q = 0; q < 2; ++q) {           // B: 32 rows x 128 cols
            int i = q * 256 + tid;
            int row = i >> 4, c8 = i & 15;
            cpa16(sb + BH_OFF + row * (BSTR * 2) + c8 * 16,
                  g_supH + gb + (size_t)row * Oo + c8 * 8);
        }
        cpa_commit();
    };

    issue(0);
    issue(1);
    for (int c = 0; c < NCH2; ++c) {
        if (c + 1 < NCH2) cpa_wait1(); else cpa_wait0();
        __syncthreads();
        if (c + 2 < NCH2) issue(c + 2);
        mma_compute1(sbase + (c % 3) * BUFSTRIDE, lane, wm, wn, acc);
    }

    // epilogue: relu + highway gate -> d_out
    #pragma unroll
    for (int mi = 0; mi < 4; ++mi) {
        #pragma unroll
        for (int ni = 0; ni < 4; ++ni) {
            int col = wn * 32 + ni * 8 + (lane & 3) * 2;
            #pragma unroll
            for (int h = 0; h < 2; ++h) {
                int row = m0 + wm * 64 + mi * 16 + (lane >> 2) + h * 8;
                float d0 = acc[mi][ni][h * 2 + 0];
                float d1 = acc[mi][ni][h * 2 + 1];
                size_t base = ((size_t)row * Bb + b) * Oo + col;
                float2 tv = *(const float2*)&g_t[base];
                float2 xv = *(const float2*)&g_h[base];
                float2 r;
                r.x = fmaxf(d0, 0.f) * tv.x + xv.x * (1.f - tv.x);
                r.y = fmaxf(d1, 0.f) * tv.y + xv.y * (1.f - tv.y);
                *(float2*)&Out[base] = r;
            }
        }
    }
}

extern "C" void kernel_launch(void* const* d_in, const int* in_sizes, int n_in,
                              void* d_out, int out_size) {
    const float* x   = (const float*)d_in[0];
    const float* adj = (const float*)d_in[1];
    const float* W1  = (const float*)d_in[2];
    const float* b1  = (const float*)d_in[3];
    const float* Wh1 = (const float*)d_in[4];
    const float* bh1 = (const float*)d_in[5];
    const float* W2  = (const float*)d_in[6];
    const float* b2  = (const float*)d_in[7];
    const float* Wh2 = (const float*)d_in[8];
    const float* bh2 = (const float*)d_in[9];
    float* out = (float*)d_out;

    static int attr_done = 0;
    if (!attr_done) {
        cudaFuncSetAttribute(gemm1_mma, cudaFuncAttributeMaxDynamicSharedMemorySize, SMEM_2B);
        cudaFuncSetAttribute(gemm2_mma, cudaFuncAttributeMaxDynamicSharedMemorySize, SMEM_2B);
        cudaFuncSetAttribute(gemm2_f16, cudaFuncAttributeMaxDynamicSharedMemorySize, SMEM_3B);
        attr_done = 1;
    }

    dim3 g1(Mrows / 128, 4);   // (256, 4)
    dim3 g2(Nn / 128, Bb);     // (4, 64)

    // Layer 1
    prep_weights<<<Ff * Jcols / 2 / 256, 256>>>(W1, b1, Wh1, bh1);
    x_split<<<Mrows * Ff / 4 / 256, 256>>>(x);
    gemm1_mma<<<g1, 256, SMEM_2B>>>(0);
    gemm2_mma<<<g2, 256, SMEM_2B>>>(adj, x);        // -> g_h, g_hH, g_adjH
    // Layer 2
    prep_weights<<<Ff * Jcols / 2 / 256, 256>>>(W2, b2, Wh2, bh2);
    gemm1_mma<<<g1, 256, SMEM_2B>>>(1);
    gemm2_f16<<<g2, 256, SMEM_3B>>>(out);           // fp16 adj -> d_out
}